// round 1
// baseline (speedup 1.0000x reference)
#include <cuda_runtime.h>
#include <math.h>
#include <stdint.h>

// ---------------- problem constants ----------------
#define B_ 2
#define E_ 256
#define NH_ 8
#define NL_ 4
#define NP_ 4
#define DF_ 1024
#define NLAYERS_ 6
#define HD_ 32
#define S_ 10548
#define M_ (B_*S_)          // 21096 query rows

__device__ __constant__ int c_LD[4] = {4, 2, 1, 1};
__device__ __constant__ int c_LH[4] = {48, 24, 12, 6};
__device__ __constant__ int c_LW[4] = {48, 24, 12, 6};

// ---------------- scratch (allocation-free) ----------------
__device__ float g_x  [M_*E_];
__device__ float g_pos[M_*E_];
__device__ float g_q  [M_*E_];
__device__ float g_val[M_*E_];
__device__ float g_sam[M_*E_];
__device__ float g_tmp[M_*E_];
__device__ float g_off [M_*(NH_*NL_*NP_*3)];
__device__ float g_attn[M_*(NH_*NL_*NP_)];
__device__ float g_hid[M_*DF_];

// ---------------- init: build x and pos from feats ----------------
__global__ void init_kernel(const float* __restrict__ f0, const float* __restrict__ p0,
                            const float* __restrict__ f1, const float* __restrict__ p1,
                            const float* __restrict__ f2, const float* __restrict__ p2,
                            const float* __restrict__ f3, const float* __restrict__ p3,
                            const float* __restrict__ le)
{
    int idx = blockIdx.x * blockDim.x + threadIdx.x;
    if (idx >= M_*E_) return;
    int e  = idx & (E_-1);
    int bs = idx >> 8;
    int b  = bs / S_;
    int s  = bs % S_;
    int lvl, i, n;
    const float *f, *p;
    if (s < 9216)       { lvl = 0; i = s;         n = 9216; f = f0; p = p0; }
    else if (s < 10368) { lvl = 1; i = s - 9216;  n = 1152; f = f1; p = p1; }
    else if (s < 10512) { lvl = 2; i = s - 10368; n = 144;  f = f2; p = p2; }
    else                { lvl = 3; i = s - 10512; n = 36;   f = f3; p = p3; }
    size_t fi = (size_t)(b*E_ + e) * n + i;
    g_x[idx]   = f[fi];
    g_pos[idx] = p[fi] + le[lvl*E_ + e];
}

// ---------------- q = x + pos ----------------
__global__ void addq_kernel()
{
    int idx = blockIdx.x * blockDim.x + threadIdx.x;
    if (idx >= M_*E_) return;
    g_q[idx] = g_x[idx] + g_pos[idx];
}

// ---------------- tiled fp32 GEMM: C = A(MxK) @ W(KxN) + bias, optional relu ----
__global__ void gemm_kernel(const float* __restrict__ A, const float* __restrict__ W,
                            const float* __restrict__ bias, float* __restrict__ C,
                            int M, int N, int K, int relu)
{
    __shared__ float As[16][64];
    __shared__ float Ws[16][64];
    int tid = threadIdx.x;
    int bm = blockIdx.y * 64;
    int bn = blockIdx.x * 64;
    int tr = (tid >> 4) * 4;
    int tc = (tid & 15) * 4;

    float acc[4][4];
    #pragma unroll
    for (int i = 0; i < 4; i++)
        #pragma unroll
        for (int j = 0; j < 4; j++) acc[i][j] = 0.f;

    int la_m = tid >> 2;
    int la_k = (tid & 3) * 4;
    int lw_k = tid >> 4;
    int lw_n = (tid & 15) * 4;
    bool a_ok = (bm + la_m) < M;
    const float* Aptr = A + (size_t)(bm + la_m) * K + la_k;
    const float* Wptr = W + (size_t)lw_k * N + bn + lw_n;

    for (int k0 = 0; k0 < K; k0 += 16) {
        float4 av = make_float4(0.f, 0.f, 0.f, 0.f);
        if (a_ok) av = *(const float4*)(Aptr + k0);
        As[la_k+0][la_m] = av.x;
        As[la_k+1][la_m] = av.y;
        As[la_k+2][la_m] = av.z;
        As[la_k+3][la_m] = av.w;
        *(float4*)&Ws[lw_k][lw_n] = *(const float4*)(Wptr + (size_t)k0 * N);
        __syncthreads();
        #pragma unroll
        for (int kk = 0; kk < 16; kk++) {
            float4 a = *(const float4*)&As[kk][tr];
            float4 b = *(const float4*)&Ws[kk][tc];
            acc[0][0] += a.x*b.x; acc[0][1] += a.x*b.y; acc[0][2] += a.x*b.z; acc[0][3] += a.x*b.w;
            acc[1][0] += a.y*b.x; acc[1][1] += a.y*b.y; acc[1][2] += a.y*b.z; acc[1][3] += a.y*b.w;
            acc[2][0] += a.z*b.x; acc[2][1] += a.z*b.y; acc[2][2] += a.z*b.z; acc[2][3] += a.z*b.w;
            acc[3][0] += a.w*b.x; acc[3][1] += a.w*b.y; acc[3][2] += a.w*b.z; acc[3][3] += a.w*b.w;
        }
        __syncthreads();
    }

    #pragma unroll
    for (int i = 0; i < 4; i++) {
        int gm = bm + tr + i;
        if (gm >= M) continue;
        #pragma unroll
        for (int j = 0; j < 4; j++) {
            float v = acc[i][j] + bias[bn + tc + j];
            if (relu) v = fmaxf(v, 0.f);
            C[(size_t)gm * N + bn + tc + j] = v;
        }
    }
}

// ---------------- deformable sampling: warp per (b,s,h), lane = HD element ----
__global__ void sample_kernel()
{
    int gwarp = (blockIdx.x * blockDim.x + threadIdx.x) >> 5;
    int lane  = threadIdx.x & 31;
    if (gwarp >= M_ * NH_) return;
    int h  = gwarp & (NH_-1);
    int bs = gwarp >> 3;
    int b  = bs / S_;
    int s  = bs % S_;

    int lvl_q, iq;
    if (s < 9216)       { lvl_q = 0; iq = s;         }
    else if (s < 10368) { lvl_q = 1; iq = s - 9216;  }
    else if (s < 10512) { lvl_q = 2; iq = s - 10368; }
    else                { lvl_q = 3; iq = s - 10512; }
    int Wq = c_LW[lvl_q], Hq = c_LH[lvl_q], Dq = c_LD[lvl_q];
    int xq = iq % Wq;
    int t  = iq / Wq;
    int yq = t % Hq;
    int zq = t / Hq;
    float rx = (xq + 0.5f) / (float)Wq;
    float ry = (yq + 0.5f) / (float)Hq;
    float rz = (zq + 0.5f) / (float)Dq;

    const float* lg = g_attn + (size_t)bs * (NH_*NL_*NP_) + h * (NL_*NP_);
    float lv[16];
    float mx = -1e30f;
    #pragma unroll
    for (int j = 0; j < 16; j++) { lv[j] = lg[j]; mx = fmaxf(mx, lv[j]); }
    float ssum = 0.f;
    #pragma unroll
    for (int j = 0; j < 16; j++) { lv[j] = expf(lv[j] - mx); ssum += lv[j]; }
    float inv = 1.f / ssum;

    const float* offp = g_off + (size_t)bs * (NH_*NL_*NP_*3) + h * (NL_*NP_*3);

    const int LDc[4]  = {4, 2, 1, 1};
    const int LHc[4]  = {48, 24, 12, 6};
    const int LWc[4]  = {48, 24, 12, 6};
    const int LS0c[4] = {0, 9216, 10368, 10512};

    float acc = 0.f;
    #pragma unroll
    for (int lvl = 0; lvl < 4; lvl++) {
        const int Dl = LDc[lvl], Hl = LHc[lvl], Wl = LWc[lvl];
        const float* vb = g_val + ((size_t)b * S_ + LS0c[lvl]) * E_ + h * HD_ + lane;
        #pragma unroll
        for (int p = 0; p < NP_; p++) {
            float aw = lv[lvl*4 + p] * inv;
            float ox = offp[lvl*12 + p*3 + 0];
            float oy = offp[lvl*12 + p*3 + 1];
            float oz = offp[lvl*12 + p*3 + 2];
            float cx = rx * (float)Wl + ox - 0.5f;
            float cy = ry * (float)Hl + oy - 0.5f;
            float cz = rz * (float)Dl + oz - 0.5f;
            float xf = floorf(cx), yf = floorf(cy), zf = floorf(cz);
            float fx = cx - xf, fy = cy - yf, fz = cz - zf;
            int x0 = (int)xf, y0 = (int)yf, z0 = (int)zf;
            #pragma unroll
            for (int dz = 0; dz < 2; dz++) {
                int iz = z0 + dz;
                if (iz < 0 || iz >= Dl) continue;
                float wz = dz ? fz : 1.f - fz;
                #pragma unroll
                for (int dy = 0; dy < 2; dy++) {
                    int iy = y0 + dy;
                    if (iy < 0 || iy >= Hl) continue;
                    float wy = dy ? fy : 1.f - fy;
                    #pragma unroll
                    for (int dx = 0; dx < 2; dx++) {
                        int ix = x0 + dx;
                        if (ix < 0 || ix >= Wl) continue;
                        float wx = dx ? fx : 1.f - fx;
                        float wgt = aw * wx * wy * wz;
                        acc += wgt * vb[(size_t)((iz*Hl + iy)*Wl + ix) * E_];
                    }
                }
            }
        }
    }
    g_sam[(size_t)bs * E_ + h * HD_ + lane] = acc;
}

// ---------------- fused residual + LayerNorm ----------------
__device__ __forceinline__ float warp_sum(float v)
{
    #pragma unroll
    for (int o = 16; o > 0; o >>= 1) v += __shfl_xor_sync(0xFFFFFFFFu, v, o);
    return v;
}

__global__ void ln_kernel(const float* __restrict__ x, const float* __restrict__ r,
                          const float* __restrict__ g, const float* __restrict__ be,
                          float* __restrict__ out)
{
    int row = blockIdx.x;
    int e = threadIdx.x;
    size_t base = (size_t)row * E_;
    float v = x[base + e] + r[base + e];
    __shared__ float sh[8];
    float ws = warp_sum(v);
    int w = e >> 5, ln = e & 31;
    if (ln == 0) sh[w] = ws;
    __syncthreads();
    float mean = 0.f;
    #pragma unroll
    for (int i = 0; i < 8; i++) mean += sh[i];
    mean *= (1.f / E_);
    __syncthreads();
    float d = v - mean;
    float ws2 = warp_sum(d * d);
    if (ln == 0) sh[w] = ws2;
    __syncthreads();
    float var = 0.f;
    #pragma unroll
    for (int i = 0; i < 8; i++) var += sh[i];
    var *= (1.f / E_);
    out[base + e] = d * rsqrtf(var + 1e-5f) * g[e] + be[e];
}

// ---------------- host launcher ----------------
extern "C" void kernel_launch(void* const* d_in, const int* in_sizes, int n_in,
                              void* d_out, int out_size)
{
    (void)in_sizes; (void)n_in; (void)out_size;
    const float* f0 = (const float*)d_in[0];
    const float* p0 = (const float*)d_in[1];
    const float* f1 = (const float*)d_in[2];
    const float* p1 = (const float*)d_in[3];
    const float* f2 = (const float*)d_in[4];
    const float* p2 = (const float*)d_in[5];
    const float* f3 = (const float*)d_in[6];
    const float* p3 = (const float*)d_in[7];
    const float* le = (const float*)d_in[8];
    const float* W_off  = (const float*)d_in[9];
    const float* b_off  = (const float*)d_in[10];
    const float* W_attn = (const float*)d_in[11];
    const float* b_attn = (const float*)d_in[12];
    const float* W_val  = (const float*)d_in[13];
    const float* b_val  = (const float*)d_in[14];
    const float* W_out  = (const float*)d_in[15];
    const float* b_out  = (const float*)d_in[16];
    const float* ln1_g  = (const float*)d_in[17];
    const float* ln1_b  = (const float*)d_in[18];
    const float* W_ff1  = (const float*)d_in[19];
    const float* b_ff1  = (const float*)d_in[20];
    const float* W_ff2  = (const float*)d_in[21];
    const float* b_ff2  = (const float*)d_in[22];
    const float* ln2_g  = (const float*)d_in[23];
    const float* ln2_b  = (const float*)d_in[24];

    float *px, *pq, *pval, *psam, *ptmp, *phid, *poff, *pattn;
    cudaGetSymbolAddress((void**)&px,    g_x);
    cudaGetSymbolAddress((void**)&pq,    g_q);
    cudaGetSymbolAddress((void**)&pval,  g_val);
    cudaGetSymbolAddress((void**)&psam,  g_sam);
    cudaGetSymbolAddress((void**)&ptmp,  g_tmp);
    cudaGetSymbolAddress((void**)&phid,  g_hid);
    cudaGetSymbolAddress((void**)&poff,  g_off);
    cudaGetSymbolAddress((void**)&pattn, g_attn);

    const int tot = M_ * E_;
    const int eb = 256;
    init_kernel<<<(tot + eb - 1) / eb, eb>>>(f0, p0, f1, p1, f2, p2, f3, p3, le);

    const int GM = (M_ + 63) / 64;   // 330
    for (int l = 0; l < NLAYERS_; l++) {
        addq_kernel<<<(tot + eb - 1) / eb, eb>>>();

        gemm_kernel<<<dim3(4, GM), 256>>>(px, W_val + (size_t)l*E_*E_, b_val + l*E_,
                                          pval, M_, E_, E_, 0);
        gemm_kernel<<<dim3(6, GM), 256>>>(pq, W_off + (size_t)l*E_*384, b_off + l*384,
                                          poff, M_, 384, E_, 0);
        gemm_kernel<<<dim3(2, GM), 256>>>(pq, W_attn + (size_t)l*E_*128, b_attn + l*128,
                                          pattn, M_, 128, E_, 0);

        sample_kernel<<<(M_ * NH_ * 32) / 256, 256>>>();

        gemm_kernel<<<dim3(4, GM), 256>>>(psam, W_out + (size_t)l*E_*E_, b_out + l*E_,
                                          ptmp, M_, E_, E_, 0);
        ln_kernel<<<M_, E_>>>(px, ptmp, ln1_g + l*E_, ln1_b + l*E_, px);

        gemm_kernel<<<dim3(16, GM), 256>>>(px, W_ff1 + (size_t)l*E_*DF_, b_ff1 + l*DF_,
                                           phid, M_, DF_, E_, 1);
        gemm_kernel<<<dim3(4, GM), 256>>>(phid, W_ff2 + (size_t)l*DF_*E_, b_ff2 + l*E_,
                                          ptmp, M_, E_, DF_, 0);

        float* lnout = (l == NLAYERS_ - 1) ? (float*)d_out : px;
        ln_kernel<<<M_, E_>>>(px, ptmp, ln2_g + l*E_, ln2_b + l*E_, lnout);
    }
}

// round 2
// speedup vs baseline: 1.7914x; 1.7914x over previous
#include <cuda_runtime.h>
#include <math.h>
#include <stdint.h>

// ---------------- problem constants ----------------
#define B_ 2
#define E_ 256
#define NH_ 8
#define NL_ 4
#define NP_ 4
#define DF_ 1024
#define NLAYERS_ 6
#define HD_ 32
#define S_ 10548
#define M_ (B_*S_)          // 21096 query rows

__device__ __constant__ int c_LD[4] = {4, 2, 1, 1};
__device__ __constant__ int c_LH[4] = {48, 24, 12, 6};
__device__ __constant__ int c_LW[4] = {48, 24, 12, 6};

// ---------------- scratch (allocation-free) ----------------
__device__ float g_x  [M_*E_];
__device__ float g_pos[M_*E_];
__device__ float g_val[M_*E_];
__device__ float g_sam[M_*E_];
__device__ float g_tmp[M_*E_];
__device__ float g_off [M_*(NH_*NL_*NP_*3)];
__device__ float g_attn[M_*(NH_*NL_*NP_)];
__device__ float g_hid[M_*DF_];

// ---------------- init: build x and pos from feats ----------------
__global__ void init_kernel(const float* __restrict__ f0, const float* __restrict__ p0,
                            const float* __restrict__ f1, const float* __restrict__ p1,
                            const float* __restrict__ f2, const float* __restrict__ p2,
                            const float* __restrict__ f3, const float* __restrict__ p3,
                            const float* __restrict__ le)
{
    int idx = blockIdx.x * blockDim.x + threadIdx.x;
    if (idx >= M_*E_) return;
    int e  = idx & (E_-1);
    int bs = idx >> 8;
    int b  = bs / S_;
    int s  = bs % S_;
    int lvl, i, n;
    const float *f, *p;
    if (s < 9216)       { lvl = 0; i = s;         n = 9216; f = f0; p = p0; }
    else if (s < 10368) { lvl = 1; i = s - 9216;  n = 1152; f = f1; p = p1; }
    else if (s < 10512) { lvl = 2; i = s - 10368; n = 144;  f = f2; p = p2; }
    else                { lvl = 3; i = s - 10512; n = 36;   f = f3; p = p3; }
    size_t fi = (size_t)(b*E_ + e) * n + i;
    g_x[idx]   = f[fi];
    g_pos[idx] = p[fi] + le[lvl*E_ + e];
}

// ---------------- tf32 helpers ----------------
__device__ __forceinline__ unsigned tf32_bits(float x)
{
    unsigned r;
    asm("cvt.rna.tf32.f32 %0, %1;\n" : "=r"(r) : "f"(x));
    return r;
}

__device__ __forceinline__ void mma_tf32(float c[4], const unsigned a[4], const unsigned b[2])
{
    asm volatile("mma.sync.aligned.m16n8k8.row.col.f32.tf32.tf32.f32 "
        "{%0,%1,%2,%3}, {%4,%5,%6,%7}, {%8,%9}, {%0,%1,%2,%3};\n"
        : "+f"(c[0]), "+f"(c[1]), "+f"(c[2]), "+f"(c[3])
        : "r"(a[0]), "r"(a[1]), "r"(a[2]), "r"(a[3]), "r"(b[0]), "r"(b[1]));
}

// ---------------- tf32 tensor-core GEMM ----------------
// C[M,N] = (A (+ A2)) @ W[K,N] + bias, optional relu.
// Block tile 128x64, BK=32, 256 threads (8 warps), warp tile 32x32.
#define BM 128
#define BN 64
#define BKt 32

__global__ void __launch_bounds__(256)
mma_gemm(const float* __restrict__ A, const float* __restrict__ A2,
         const float* __restrict__ W, const float* __restrict__ bias,
         float* __restrict__ C, int M, int N, int K, int relu)
{
    // A smem [m][k], stride 36 (≡4 mod 32 -> frag banks 4q+r distinct)
    // B smem [k][n], stride 72 (≡8 mod 32 -> frag banks 8r+q distinct)
    __shared__ __align__(16) float As[BM][36];
    __shared__ __align__(16) float Bs[BKt][72];

    int tid  = threadIdx.x;
    int lane = tid & 31;
    int wid  = tid >> 5;
    int bm = blockIdx.y * BM;
    int bn = blockIdx.x * BN;
    int wm = (wid >> 1) * 32;   // 4 warps along M
    int wn = (wid & 1) * 32;    // 2 warps along N
    int q = lane >> 2;          // 0..7
    int r = lane & 3;           // 0..3

    float acc[2][4][4];
    #pragma unroll
    for (int mi = 0; mi < 2; mi++)
        #pragma unroll
        for (int ni = 0; ni < 4; ni++)
            #pragma unroll
            for (int j = 0; j < 4; j++) acc[mi][ni][j] = 0.f;

    // global-load index maps
    // A tile: 128x32 -> 1024 float4, 4 per thread
    int arow[4], ac4[4];
    #pragma unroll
    for (int i = 0; i < 4; i++) { int idx = tid + i*256; arow[i] = idx >> 3; ac4[i] = idx & 7; }
    // B tile: 32x64 -> 512 float4, 2 per thread
    int brow[2], bc4[2];
    #pragma unroll
    for (int i = 0; i < 2; i++) { int idx = tid + i*256; brow[i] = idx >> 4; bc4[i] = idx & 15; }

    float4 pa[4], pb[2];
    const float4 zero4 = make_float4(0.f,0.f,0.f,0.f);

    // prefetch kt = 0
    #pragma unroll
    for (int i = 0; i < 4; i++) {
        int gm = bm + arow[i];
        if (gm < M) {
            const float* ap = A + (size_t)gm * K + ac4[i]*4;
            float4 v = *(const float4*)ap;
            if (A2) {
                float4 v2 = *(const float4*)(A2 + (size_t)gm * K + ac4[i]*4);
                v.x += v2.x; v.y += v2.y; v.z += v2.z; v.w += v2.w;
            }
            pa[i] = v;
        } else pa[i] = zero4;
    }
    #pragma unroll
    for (int i = 0; i < 2; i++)
        pb[i] = *(const float4*)(W + (size_t)brow[i] * N + bn + bc4[i]*4);

    for (int kt = 0; kt < K; kt += BKt) {
        // store (tf32-rounded) to smem
        #pragma unroll
        for (int i = 0; i < 4; i++) {
            float4 w;
            w.x = __uint_as_float(tf32_bits(pa[i].x));
            w.y = __uint_as_float(tf32_bits(pa[i].y));
            w.z = __uint_as_float(tf32_bits(pa[i].z));
            w.w = __uint_as_float(tf32_bits(pa[i].w));
            *(float4*)&As[arow[i]][ac4[i]*4] = w;
        }
        #pragma unroll
        for (int i = 0; i < 2; i++) {
            float4 w;
            w.x = __uint_as_float(tf32_bits(pb[i].x));
            w.y = __uint_as_float(tf32_bits(pb[i].y));
            w.z = __uint_as_float(tf32_bits(pb[i].z));
            w.w = __uint_as_float(tf32_bits(pb[i].w));
            *(float4*)&Bs[brow[i]][bc4[i]*4] = w;
        }
        __syncthreads();

        // prefetch next tile
        if (kt + BKt < K) {
            #pragma unroll
            for (int i = 0; i < 4; i++) {
                int gm = bm + arow[i];
                if (gm < M) {
                    const float* ap = A + (size_t)gm * K + kt + BKt + ac4[i]*4;
                    float4 v = *(const float4*)ap;
                    if (A2) {
                        float4 v2 = *(const float4*)(A2 + (size_t)gm * K + kt + BKt + ac4[i]*4);
                        v.x += v2.x; v.y += v2.y; v.z += v2.z; v.w += v2.w;
                    }
                    pa[i] = v;
                } else pa[i] = zero4;
            }
            #pragma unroll
            for (int i = 0; i < 2; i++)
                pb[i] = *(const float4*)(W + (size_t)(kt + BKt + brow[i]) * N + bn + bc4[i]*4);
        }

        // compute: 4 k-steps of 8
        #pragma unroll
        for (int ks = 0; ks < 4; ks++) {
            unsigned af[2][4], bf[4][2];
            #pragma unroll
            for (int mi = 0; mi < 2; mi++) {
                int m0 = wm + mi*16 + q;
                af[mi][0] = __float_as_uint(As[m0    ][ks*8 + r    ]);
                af[mi][1] = __float_as_uint(As[m0 + 8][ks*8 + r    ]);
                af[mi][2] = __float_as_uint(As[m0    ][ks*8 + r + 4]);
                af[mi][3] = __float_as_uint(As[m0 + 8][ks*8 + r + 4]);
            }
            #pragma unroll
            for (int ni = 0; ni < 4; ni++) {
                bf[ni][0] = __float_as_uint(Bs[ks*8 + r    ][wn + ni*8 + q]);
                bf[ni][1] = __float_as_uint(Bs[ks*8 + r + 4][wn + ni*8 + q]);
            }
            #pragma unroll
            for (int mi = 0; mi < 2; mi++)
                #pragma unroll
                for (int ni = 0; ni < 4; ni++)
                    mma_tf32(acc[mi][ni], af[mi], bf[ni]);
        }
        __syncthreads();
    }

    // epilogue
    #pragma unroll
    for (int mi = 0; mi < 2; mi++) {
        #pragma unroll
        for (int ni = 0; ni < 4; ni++) {
            int row = bm + wm + mi*16 + q;
            int col = bn + wn + ni*8 + r*2;
            float bx = bias[col], by = bias[col+1];
            if (row < M) {
                float v0 = acc[mi][ni][0] + bx;
                float v1 = acc[mi][ni][1] + by;
                if (relu) { v0 = fmaxf(v0, 0.f); v1 = fmaxf(v1, 0.f); }
                *(float2*)&C[(size_t)row * N + col] = make_float2(v0, v1);
            }
            if (row + 8 < M) {
                float v2 = acc[mi][ni][2] + bx;
                float v3 = acc[mi][ni][3] + by;
                if (relu) { v2 = fmaxf(v2, 0.f); v3 = fmaxf(v3, 0.f); }
                *(float2*)&C[(size_t)(row + 8) * N + col] = make_float2(v2, v3);
            }
        }
    }
}

// ---------------- deformable sampling: warp per (b,s,h), lane = HD element ----
__global__ void sample_kernel()
{
    int gwarp = (blockIdx.x * blockDim.x + threadIdx.x) >> 5;
    int lane  = threadIdx.x & 31;
    if (gwarp >= M_ * NH_) return;
    int h  = gwarp & (NH_-1);
    int bs = gwarp >> 3;
    int b  = bs / S_;
    int s  = bs % S_;

    int lvl_q, iq;
    if (s < 9216)       { lvl_q = 0; iq = s;         }
    else if (s < 10368) { lvl_q = 1; iq = s - 9216;  }
    else if (s < 10512) { lvl_q = 2; iq = s - 10368; }
    else                { lvl_q = 3; iq = s - 10512; }
    int Wq = c_LW[lvl_q], Hq = c_LH[lvl_q], Dq = c_LD[lvl_q];
    int xq = iq % Wq;
    int t  = iq / Wq;
    int yq = t % Hq;
    int zq = t / Hq;
    float rx = (xq + 0.5f) / (float)Wq;
    float ry = (yq + 0.5f) / (float)Hq;
    float rz = (zq + 0.5f) / (float)Dq;

    const float* lg = g_attn + (size_t)bs * (NH_*NL_*NP_) + h * (NL_*NP_);
    float lv[16];
    float mx = -1e30f;
    #pragma unroll
    for (int j = 0; j < 16; j++) { lv[j] = lg[j]; mx = fmaxf(mx, lv[j]); }
    float ssum = 0.f;
    #pragma unroll
    for (int j = 0; j < 16; j++) { lv[j] = expf(lv[j] - mx); ssum += lv[j]; }
    float inv = 1.f / ssum;

    const float* offp = g_off + (size_t)bs * (NH_*NL_*NP_*3) + h * (NL_*NP_*3);

    const int LDc[4]  = {4, 2, 1, 1};
    const int LHc[4]  = {48, 24, 12, 6};
    const int LWc[4]  = {48, 24, 12, 6};
    const int LS0c[4] = {0, 9216, 10368, 10512};

    float acc = 0.f;
    #pragma unroll
    for (int lvl = 0; lvl < 4; lvl++) {
        const int Dl = LDc[lvl], Hl = LHc[lvl], Wl = LWc[lvl];
        const float* vb = g_val + ((size_t)b * S_ + LS0c[lvl]) * E_ + h * HD_ + lane;
        #pragma unroll
        for (int p = 0; p < NP_; p++) {
            float aw = lv[lvl*4 + p] * inv;
            float ox = offp[lvl*12 + p*3 + 0];
            float oy = offp[lvl*12 + p*3 + 1];
            float oz = offp[lvl*12 + p*3 + 2];
            float cx = rx * (float)Wl + ox - 0.5f;
            float cy = ry * (float)Hl + oy - 0.5f;
            float cz = rz * (float)Dl + oz - 0.5f;
            float xf = floorf(cx), yf = floorf(cy), zf = floorf(cz);
            float fx = cx - xf, fy = cy - yf, fz = cz - zf;
            int x0 = (int)xf, y0 = (int)yf, z0 = (int)zf;
            #pragma unroll
            for (int dz = 0; dz < 2; dz++) {
                int iz = z0 + dz;
                if (iz < 0 || iz >= Dl) continue;
                float wz = dz ? fz : 1.f - fz;
                #pragma unroll
                for (int dy = 0; dy < 2; dy++) {
                    int iy = y0 + dy;
                    if (iy < 0 || iy >= Hl) continue;
                    float wy = dy ? fy : 1.f - fy;
                    #pragma unroll
                    for (int dx = 0; dx < 2; dx++) {
                        int ix = x0 + dx;
                        if (ix < 0 || ix >= Wl) continue;
                        float wx = dx ? fx : 1.f - fx;
                        float wgt = aw * wx * wy * wz;
                        acc += wgt * vb[(size_t)((iz*Hl + iy)*Wl + ix) * E_];
                    }
                }
            }
        }
    }
    g_sam[(size_t)bs * E_ + h * HD_ + lane] = acc;
}

// ---------------- fused residual + LayerNorm ----------------
__device__ __forceinline__ float warp_sum(float v)
{
    #pragma unroll
    for (int o = 16; o > 0; o >>= 1) v += __shfl_xor_sync(0xFFFFFFFFu, v, o);
    return v;
}

__global__ void ln_kernel(const float* __restrict__ x, const float* __restrict__ r,
                          const float* __restrict__ g, const float* __restrict__ be,
                          float* __restrict__ out)
{
    int row = blockIdx.x;
    int e = threadIdx.x;
    size_t base = (size_t)row * E_;
    float v = x[base + e] + r[base + e];
    __shared__ float sh[8];
    float ws = warp_sum(v);
    int w = e >> 5, ln = e & 31;
    if (ln == 0) sh[w] = ws;
    __syncthreads();
    float mean = 0.f;
    #pragma unroll
    for (int i = 0; i < 8; i++) mean += sh[i];
    mean *= (1.f / E_);
    __syncthreads();
    float d = v - mean;
    float ws2 = warp_sum(d * d);
    if (ln == 0) sh[w] = ws2;
    __syncthreads();
    float var = 0.f;
    #pragma unroll
    for (int i = 0; i < 8; i++) var += sh[i];
    var *= (1.f / E_);
    out[base + e] = d * rsqrtf(var + 1e-5f) * g[e] + be[e];
}

// ---------------- host launcher ----------------
extern "C" void kernel_launch(void* const* d_in, const int* in_sizes, int n_in,
                              void* d_out, int out_size)
{
    (void)in_sizes; (void)n_in; (void)out_size;
    const float* f0 = (const float*)d_in[0];
    const float* p0 = (const float*)d_in[1];
    const float* f1 = (const float*)d_in[2];
    const float* p1 = (const float*)d_in[3];
    const float* f2 = (const float*)d_in[4];
    const float* p2 = (const float*)d_in[5];
    const float* f3 = (const float*)d_in[6];
    const float* p3 = (const float*)d_in[7];
    const float* le = (const float*)d_in[8];
    const float* W_off  = (const float*)d_in[9];
    const float* b_off  = (const float*)d_in[10];
    const float* W_attn = (const float*)d_in[11];
    const float* b_attn = (const float*)d_in[12];
    const float* W_val  = (const float*)d_in[13];
    const float* b_val  = (const float*)d_in[14];
    const float* W_out  = (const float*)d_in[15];
    const float* b_out  = (const float*)d_in[16];
    const float* ln1_g  = (const float*)d_in[17];
    const float* ln1_b  = (const float*)d_in[18];
    const float* W_ff1  = (const float*)d_in[19];
    const float* b_ff1  = (const float*)d_in[20];
    const float* W_ff2  = (const float*)d_in[21];
    const float* b_ff2  = (const float*)d_in[22];
    const float* ln2_g  = (const float*)d_in[23];
    const float* ln2_b  = (const float*)d_in[24];

    float *px, *ppos, *pval, *psam, *ptmp, *phid, *poff, *pattn;
    cudaGetSymbolAddress((void**)&px,    g_x);
    cudaGetSymbolAddress((void**)&ppos,  g_pos);
    cudaGetSymbolAddress((void**)&pval,  g_val);
    cudaGetSymbolAddress((void**)&psam,  g_sam);
    cudaGetSymbolAddress((void**)&ptmp,  g_tmp);
    cudaGetSymbolAddress((void**)&phid,  g_hid);
    cudaGetSymbolAddress((void**)&poff,  g_off);
    cudaGetSymbolAddress((void**)&pattn, g_attn);

    const int tot = M_ * E_;
    const int eb = 256;
    init_kernel<<<(tot + eb - 1) / eb, eb>>>(f0, p0, f1, p1, f2, p2, f3, p3, le);

    const int GM = (M_ + BM - 1) / BM;   // 165
    for (int l = 0; l < NLAYERS_; l++) {
        // value proj (A = x)
        mma_gemm<<<dim3(E_/BN, GM), 256>>>(px, nullptr, W_val + (size_t)l*E_*E_,
                                           b_val + l*E_, pval, M_, E_, E_, 0);
        // offsets (A = x + pos, fused)
        mma_gemm<<<dim3(384/BN, GM), 256>>>(px, ppos, W_off + (size_t)l*E_*384,
                                            b_off + l*384, poff, M_, 384, E_, 0);
        // attn logits (A = x + pos, fused)
        mma_gemm<<<dim3(128/BN, GM), 256>>>(px, ppos, W_attn + (size_t)l*E_*128,
                                            b_attn + l*128, pattn, M_, 128, E_, 0);

        sample_kernel<<<(M_ * NH_ * 32) / 256, 256>>>();

        mma_gemm<<<dim3(E_/BN, GM), 256>>>(psam, nullptr, W_out + (size_t)l*E_*E_,
                                           b_out + l*E_, ptmp, M_, E_, E_, 0);
        ln_kernel<<<M_, E_>>>(px, ptmp, ln1_g + l*E_, ln1_b + l*E_, px);

        mma_gemm<<<dim3(DF_/BN, GM), 256>>>(px, nullptr, W_ff1 + (size_t)l*E_*DF_,
                                            b_ff1 + l*DF_, phid, M_, DF_, E_, 1);
        mma_gemm<<<dim3(E_/BN, GM), 256>>>(phid, nullptr, W_ff2 + (size_t)l*DF_*E_,
                                           b_ff2 + l*E_, ptmp, M_, E_, DF_, 0);

        float* lnout = (l == NLAYERS_ - 1) ? (float*)d_out : px;
        ln_kernel<<<M_, E_>>>(px, ptmp, ln2_g + l*E_, ln2_b + l*E_, lnout);
    }
}

// round 3
// speedup vs baseline: 1.8955x; 1.0581x over previous
#include <cuda_runtime.h>
#include <math.h>
#include <stdint.h>

// ---------------- problem constants ----------------
#define B_ 2
#define E_ 256
#define NH_ 8
#define NL_ 4
#define NP_ 4
#define DF_ 1024
#define NLAYERS_ 6
#define HD_ 32
#define S_ 10548
#define M_ (B_*S_)          // 21096 query rows

__device__ __constant__ int c_LD[4] = {4, 2, 1, 1};
__device__ __constant__ int c_LH[4] = {48, 24, 12, 6};
__device__ __constant__ int c_LW[4] = {48, 24, 12, 6};

// ---------------- scratch (allocation-free) ----------------
__device__ float g_x  [M_*E_];
__device__ float g_pos[M_*E_];
__device__ float g_q  [M_*E_];
__device__ float g_val[M_*E_];
__device__ float g_sam[M_*E_];
__device__ float g_tmp[M_*E_];
__device__ float g_off [M_*(NH_*NL_*NP_*3)];
__device__ float g_attn[M_*(NH_*NL_*NP_)];
__device__ float g_hid[M_*DF_];

// ---------------- coalesced transposing init (per level) ----------------
// f,p: [B, E, n] -> g_x/g_pos rows (b*S + s0 + i), col e ; pos += le[e]
__global__ void init_t_kernel(const float* __restrict__ f, const float* __restrict__ p,
                              const float* __restrict__ le_row, int n, int s0)
{
    __shared__ float tf[32][33];
    __shared__ float tp[32][33];
    int i0 = blockIdx.x * 32;
    int e0 = blockIdx.y * 32;
    int b  = blockIdx.z;
    int tx = threadIdx.x, ty = threadIdx.y;

    int ig = i0 + tx;
    int eg = e0 + ty;
    if (ig < n) {
        size_t src = (size_t)(b*E_ + eg) * n + ig;
        tf[ty][tx] = f[src];
        tp[ty][tx] = p[src];
    }
    __syncthreads();

    int iw = i0 + ty;
    int ew = e0 + tx;
    if (iw < n) {
        size_t dst = (size_t)(b*S_ + s0 + iw) * E_ + ew;
        g_x[dst]   = tf[tx][ty];
        g_pos[dst] = tp[tx][ty] + le_row[ew];
    }
}

// ---------------- q = x + pos (vectorized) ----------------
__global__ void addq_kernel()
{
    int idx = blockIdx.x * blockDim.x + threadIdx.x;
    if (idx >= M_*E_/4) return;
    float4 a = ((const float4*)g_x)[idx];
    float4 b = ((const float4*)g_pos)[idx];
    a.x += b.x; a.y += b.y; a.z += b.z; a.w += b.w;
    ((float4*)g_q)[idx] = a;
}

// ---------------- tf32 helpers ----------------
__device__ __forceinline__ unsigned tf32_bits(float x)
{
    unsigned r;
    asm("cvt.rna.tf32.f32 %0, %1;\n" : "=r"(r) : "f"(x));
    return r;
}

__device__ __forceinline__ void mma_tf32(float c[4], const unsigned a[4], const unsigned b[2])
{
    asm volatile("mma.sync.aligned.m16n8k8.row.col.f32.tf32.tf32.f32 "
        "{%0,%1,%2,%3}, {%4,%5,%6,%7}, {%8,%9}, {%0,%1,%2,%3};\n"
        : "+f"(c[0]), "+f"(c[1]), "+f"(c[2]), "+f"(c[3])
        : "r"(a[0]), "r"(a[1]), "r"(a[2]), "r"(a[3]), "r"(b[0]), "r"(b[1]));
}

__device__ __forceinline__ void cp_async16(float* smem, const float* gmem, bool valid)
{
    unsigned saddr = (unsigned)__cvta_generic_to_shared(smem);
    int sz = valid ? 16 : 0;
    asm volatile("cp.async.cg.shared.global [%0], [%1], 16, %2;\n"
                 :: "r"(saddr), "l"(gmem), "r"(sz));
}
__device__ __forceinline__ void cp_commit() { asm volatile("cp.async.commit_group;\n"); }
template<int N> __device__ __forceinline__ void cp_wait() { asm volatile("cp.async.wait_group %0;\n" :: "n"(N)); }

// ---------------- tf32 tensor-core GEMM, cp.async 2-stage ----------------
// C[M,N] = A @ W[K,N] + bias, optional relu. 256 thr, BM=128 BN=64 BK=32.
#define BM 128
#define BN 64
#define BK 32
#define ASTRIDE 36
#define BSTRIDE 72
#define A_ST (BM*ASTRIDE)           // 4608 floats
#define B_ST (BK*BSTRIDE)           // 2304 floats
#define STAGE_FL (A_ST + B_ST)      // 6912 floats
#define GEMM_SMEM (2*STAGE_FL*4)    // 55296 bytes

__global__ void __launch_bounds__(256, 3)
mma_gemm(const float* __restrict__ A, const float* __restrict__ W,
         const float* __restrict__ bias, float* __restrict__ C,
         int M, int N, int K, int relu)
{
    extern __shared__ float smp[];

    int tid  = threadIdx.x;
    int lane = tid & 31;
    int wid  = tid >> 5;
    int bm = blockIdx.y * BM;
    int bn = blockIdx.x * BN;
    int wm = (wid >> 1) * 32;   // 4 warps along M
    int wn = (wid & 1) * 32;    // 2 warps along N
    int q = lane >> 2;          // 0..7
    int r = lane & 3;           // 0..3

    float acc[2][4][4];
    #pragma unroll
    for (int mi = 0; mi < 2; mi++)
        #pragma unroll
        for (int ni = 0; ni < 4; ni++)
            #pragma unroll
            for (int j = 0; j < 4; j++) acc[mi][ni][j] = 0.f;

    // load maps: A tile 128x32 = 1024 16B-chunks (4/thread); B 32x64 = 512 (2/thread)
    int arow[4], ac4[4]; bool aval[4];
    #pragma unroll
    for (int i = 0; i < 4; i++) {
        int idx = tid + i*256; arow[i] = idx >> 3; ac4[i] = idx & 7;
        aval[i] = (bm + arow[i]) < M;
    }
    int brow[2], bc4[2];
    #pragma unroll
    for (int i = 0; i < 2; i++) { int idx = tid + i*256; brow[i] = idx >> 4; bc4[i] = idx & 15; }

    int nkt = K / BK;

    // issue stage 0
    {
        float* As = smp;
        float* Bs = smp + A_ST;
        #pragma unroll
        for (int i = 0; i < 4; i++)
            cp_async16(As + arow[i]*ASTRIDE + ac4[i]*4,
                       A + (size_t)(aval[i] ? (bm + arow[i]) : 0) * K + ac4[i]*4, aval[i]);
        #pragma unroll
        for (int i = 0; i < 2; i++)
            cp_async16(Bs + brow[i]*BSTRIDE + bc4[i]*4,
                       W + (size_t)brow[i] * N + bn + bc4[i]*4, true);
        cp_commit();
    }

    for (int kt = 0; kt < nkt; kt++) {
        int cur = kt & 1;
        // issue next stage
        if (kt + 1 < nkt) {
            float* As = smp + (cur ^ 1) * STAGE_FL;
            float* Bs = As + A_ST;
            int kg = (kt + 1) * BK;
            #pragma unroll
            for (int i = 0; i < 4; i++)
                cp_async16(As + arow[i]*ASTRIDE + ac4[i]*4,
                           A + (size_t)(aval[i] ? (bm + arow[i]) : 0) * K + kg + ac4[i]*4, aval[i]);
            #pragma unroll
            for (int i = 0; i < 2; i++)
                cp_async16(Bs + brow[i]*BSTRIDE + bc4[i]*4,
                           W + (size_t)(kg + brow[i]) * N + bn + bc4[i]*4, true);
            cp_commit();
            cp_wait<1>();
        } else {
            cp_wait<0>();
        }
        __syncthreads();

        const float* As = smp + cur * STAGE_FL;
        const float* Bs = As + A_ST;

        #pragma unroll
        for (int ks = 0; ks < 4; ks++) {
            unsigned af[2][4], bf[4][2];
            #pragma unroll
            for (int mi = 0; mi < 2; mi++) {
                int m0 = wm + mi*16 + q;
                af[mi][0] = tf32_bits(As[(m0    )*ASTRIDE + ks*8 + r    ]);
                af[mi][1] = tf32_bits(As[(m0 + 8)*ASTRIDE + ks*8 + r    ]);
                af[mi][2] = tf32_bits(As[(m0    )*ASTRIDE + ks*8 + r + 4]);
                af[mi][3] = tf32_bits(As[(m0 + 8)*ASTRIDE + ks*8 + r + 4]);
            }
            #pragma unroll
            for (int ni = 0; ni < 4; ni++) {
                bf[ni][0] = tf32_bits(Bs[(ks*8 + r    )*BSTRIDE + wn + ni*8 + q]);
                bf[ni][1] = tf32_bits(Bs[(ks*8 + r + 4)*BSTRIDE + wn + ni*8 + q]);
            }
            #pragma unroll
            for (int mi = 0; mi < 2; mi++)
                #pragma unroll
                for (int ni = 0; ni < 4; ni++)
                    mma_tf32(acc[mi][ni], af[mi], bf[ni]);
        }
        __syncthreads();
    }

    // epilogue
    #pragma unroll
    for (int mi = 0; mi < 2; mi++) {
        #pragma unroll
        for (int ni = 0; ni < 4; ni++) {
            int row = bm + wm + mi*16 + q;
            int col = bn + wn + ni*8 + r*2;
            float bx = bias[col], by = bias[col+1];
            if (row < M) {
                float v0 = acc[mi][ni][0] + bx;
                float v1 = acc[mi][ni][1] + by;
                if (relu) { v0 = fmaxf(v0, 0.f); v1 = fmaxf(v1, 0.f); }
                *(float2*)&C[(size_t)row * N + col] = make_float2(v0, v1);
            }
            if (row + 8 < M) {
                float v2 = acc[mi][ni][2] + bx;
                float v3 = acc[mi][ni][3] + by;
                if (relu) { v2 = fmaxf(v2, 0.f); v3 = fmaxf(v3, 0.f); }
                *(float2*)&C[(size_t)(row + 8) * N + col] = make_float2(v2, v3);
            }
        }
    }
}

// ---------------- deformable sampling: warp per (b,s,h), lane = HD element ----
__global__ void sample_kernel()
{
    int gwarp = (blockIdx.x * blockDim.x + threadIdx.x) >> 5;
    int lane  = threadIdx.x & 31;
    if (gwarp >= M_ * NH_) return;
    int h  = gwarp & (NH_-1);
    int bs = gwarp >> 3;
    int b  = bs / S_;
    int s  = bs % S_;

    int lvl_q, iq;
    if (s < 9216)       { lvl_q = 0; iq = s;         }
    else if (s < 10368) { lvl_q = 1; iq = s - 9216;  }
    else if (s < 10512) { lvl_q = 2; iq = s - 10368; }
    else                { lvl_q = 3; iq = s - 10512; }
    int Wq = c_LW[lvl_q], Hq = c_LH[lvl_q], Dq = c_LD[lvl_q];
    int xq = iq % Wq;
    int t  = iq / Wq;
    int yq = t % Hq;
    int zq = t / Hq;
    float rx = (xq + 0.5f) / (float)Wq;
    float ry = (yq + 0.5f) / (float)Hq;
    float rz = (zq + 0.5f) / (float)Dq;

    const float* lg = g_attn + (size_t)bs * (NH_*NL_*NP_) + h * (NL_*NP_);
    float lv[16];
    float mx = -1e30f;
    #pragma unroll
    for (int j = 0; j < 16; j++) { lv[j] = lg[j]; mx = fmaxf(mx, lv[j]); }
    float ssum = 0.f;
    #pragma unroll
    for (int j = 0; j < 16; j++) { lv[j] = expf(lv[j] - mx); ssum += lv[j]; }
    float inv = 1.f / ssum;

    const float* offp = g_off + (size_t)bs * (NH_*NL_*NP_*3) + h * (NL_*NP_*3);

    const int LDc[4]  = {4, 2, 1, 1};
    const int LHc[4]  = {48, 24, 12, 6};
    const int LWc[4]  = {48, 24, 12, 6};
    const int LS0c[4] = {0, 9216, 10368, 10512};

    float acc = 0.f;
    #pragma unroll
    for (int lvl = 0; lvl < 4; lvl++) {
        const int Dl = LDc[lvl], Hl = LHc[lvl], Wl = LWc[lvl];
        const float* vb = g_val + ((size_t)b * S_ + LS0c[lvl]) * E_ + h * HD_ + lane;
        #pragma unroll
        for (int p = 0; p < NP_; p++) {
            float aw = lv[lvl*4 + p] * inv;
            float ox = offp[lvl*12 + p*3 + 0];
            float oy = offp[lvl*12 + p*3 + 1];
            float oz = offp[lvl*12 + p*3 + 2];
            float cx = rx * (float)Wl + ox - 0.5f;
            float cy = ry * (float)Hl + oy - 0.5f;
            float cz = rz * (float)Dl + oz - 0.5f;
            float xf = floorf(cx), yf = floorf(cy), zf = floorf(cz);
            float fx = cx - xf, fy = cy - yf, fz = cz - zf;
            int x0 = (int)xf, y0 = (int)yf, z0 = (int)zf;
            #pragma unroll
            for (int dz = 0; dz < 2; dz++) {
                int iz = z0 + dz;
                if (iz < 0 || iz >= Dl) continue;
                float wz = dz ? fz : 1.f - fz;
                #pragma unroll
                for (int dy = 0; dy < 2; dy++) {
                    int iy = y0 + dy;
                    if (iy < 0 || iy >= Hl) continue;
                    float wy = dy ? fy : 1.f - fy;
                    #pragma unroll
                    for (int dx = 0; dx < 2; dx++) {
                        int ix = x0 + dx;
                        if (ix < 0 || ix >= Wl) continue;
                        float wx = dx ? fx : 1.f - fx;
                        float wgt = aw * wx * wy * wz;
                        acc += wgt * vb[(size_t)((iz*Hl + iy)*Wl + ix) * E_];
                    }
                }
            }
        }
    }
    g_sam[(size_t)bs * E_ + h * HD_ + lane] = acc;
}

// ---------------- fused residual + LayerNorm ----------------
__device__ __forceinline__ float warp_sum(float v)
{
    #pragma unroll
    for (int o = 16; o > 0; o >>= 1) v += __shfl_xor_sync(0xFFFFFFFFu, v, o);
    return v;
}

__global__ void ln_kernel(const float* __restrict__ x, const float* __restrict__ r,
                          const float* __restrict__ g, const float* __restrict__ be,
                          float* __restrict__ out)
{
    int row = blockIdx.x;
    int e = threadIdx.x;
    size_t base = (size_t)row * E_;
    float v = x[base + e] + r[base + e];
    __shared__ float sh[8];
    float ws = warp_sum(v);
    int w = e >> 5, ln = e & 31;
    if (ln == 0) sh[w] = ws;
    __syncthreads();
    float mean = 0.f;
    #pragma unroll
    for (int i = 0; i < 8; i++) mean += sh[i];
    mean *= (1.f / E_);
    __syncthreads();
    float d = v - mean;
    float ws2 = warp_sum(d * d);
    if (ln == 0) sh[w] = ws2;
    __syncthreads();
    float var = 0.f;
    #pragma unroll
    for (int i = 0; i < 8; i++) var += sh[i];
    var *= (1.f / E_);
    out[base + e] = d * rsqrtf(var + 1e-5f) * g[e] + be[e];
}

// ---------------- host launcher ----------------
extern "C" void kernel_launch(void* const* d_in, const int* in_sizes, int n_in,
                              void* d_out, int out_size)
{
    (void)in_sizes; (void)n_in; (void)out_size;
    const float* f0 = (const float*)d_in[0];
    const float* p0 = (const float*)d_in[1];
    const float* f1 = (const float*)d_in[2];
    const float* p1 = (const float*)d_in[3];
    const float* f2 = (const float*)d_in[4];
    const float* p2 = (const float*)d_in[5];
    const float* f3 = (const float*)d_in[6];
    const float* p3 = (const float*)d_in[7];
    const float* le = (const float*)d_in[8];
    const float* W_off  = (const float*)d_in[9];
    const float* b_off  = (const float*)d_in[10];
    const float* W_attn = (const float*)d_in[11];
    const float* b_attn = (const float*)d_in[12];
    const float* W_val  = (const float*)d_in[13];
    const float* b_val  = (const float*)d_in[14];
    const float* W_out  = (const float*)d_in[15];
    const float* b_out  = (const float*)d_in[16];
    const float* ln1_g  = (const float*)d_in[17];
    const float* ln1_b  = (const float*)d_in[18];
    const float* W_ff1  = (const float*)d_in[19];
    const float* b_ff1  = (const float*)d_in[20];
    const float* W_ff2  = (const float*)d_in[21];
    const float* b_ff2  = (const float*)d_in[22];
    const float* ln2_g  = (const float*)d_in[23];
    const float* ln2_b  = (const float*)d_in[24];

    float *px, *ppos, *pq, *pval, *psam, *ptmp, *phid, *poff, *pattn;
    cudaGetSymbolAddress((void**)&px,    g_x);
    cudaGetSymbolAddress((void**)&ppos,  g_pos);
    cudaGetSymbolAddress((void**)&pq,    g_q);
    cudaGetSymbolAddress((void**)&pval,  g_val);
    cudaGetSymbolAddress((void**)&psam,  g_sam);
    cudaGetSymbolAddress((void**)&ptmp,  g_tmp);
    cudaGetSymbolAddress((void**)&phid,  g_hid);
    cudaGetSymbolAddress((void**)&poff,  g_off);
    cudaGetSymbolAddress((void**)&pattn, g_attn);

    cudaFuncSetAttribute(mma_gemm, cudaFuncAttributeMaxDynamicSharedMemorySize, GEMM_SMEM);

    // transposing init, one launch per level
    {
        dim3 blk(32, 32);
        init_t_kernel<<<dim3(288, 8, B_), blk>>>(f0, p0, le + 0*E_, 9216, 0);
        init_t_kernel<<<dim3( 36, 8, B_), blk>>>(f1, p1, le + 1*E_, 1152, 9216);
        init_t_kernel<<<dim3(  5, 8, B_), blk>>>(f2, p2, le + 2*E_,  144, 10368);
        init_t_kernel<<<dim3(  2, 8, B_), blk>>>(f3, p3, le + 3*E_,   36, 10512);
    }

    const int GM = (M_ + BM - 1) / BM;   // 165
    for (int l = 0; l < NLAYERS_; l++) {
        addq_kernel<<<(M_*E_/4 + 255)/256, 256>>>();

        mma_gemm<<<dim3(E_/BN, GM), 256, GEMM_SMEM>>>(px, W_val + (size_t)l*E_*E_,
                                           b_val + l*E_, pval, M_, E_, E_, 0);
        mma_gemm<<<dim3(384/BN, GM), 256, GEMM_SMEM>>>(pq, W_off + (size_t)l*E_*384,
                                            b_off + l*384, poff, M_, 384, E_, 0);
        mma_gemm<<<dim3(128/BN, GM), 256, GEMM_SMEM>>>(pq, W_attn + (size_t)l*E_*128,
                                            b_attn + l*128, pattn, M_, 128, E_, 0);

        sample_kernel<<<(M_ * NH_ * 32) / 256, 256>>>();

        mma_gemm<<<dim3(E_/BN, GM), 256, GEMM_SMEM>>>(psam, W_out + (size_t)l*E_*E_,
                                           b_out + l*E_, ptmp, M_, E_, E_, 0);
        ln_kernel<<<M_, E_>>>(px, ptmp, ln1_g + l*E_, ln1_b + l*E_, px);

        mma_gemm<<<dim3(DF_/BN, GM), 256, GEMM_SMEM>>>(px, W_ff1 + (size_t)l*E_*DF_,
                                            b_ff1 + l*DF_, phid, M_, DF_, E_, 1);
        mma_gemm<<<dim3(E_/BN, GM), 256, GEMM_SMEM>>>(phid, W_ff2 + (size_t)l*DF_*E_,
                                           b_ff2 + l*E_, ptmp, M_, E_, DF_, 0);

        float* lnout = (l == NLAYERS_ - 1) ? (float*)d_out : px;
        ln_kernel<<<M_, E_>>>(px, ptmp, ln2_g + l*E_, ln2_b + l*E_, lnout);
    }
}

// round 4
// speedup vs baseline: 2.0319x; 1.0719x over previous
#include <cuda_runtime.h>
#include <math.h>
#include <stdint.h>

// ---------------- problem constants ----------------
#define B_ 2
#define E_ 256
#define NH_ 8
#define NL_ 4
#define NP_ 4
#define DF_ 1024
#define NLAYERS_ 6
#define HD_ 32
#define S_ 10548
#define M_ (B_*S_)          // 21096 query rows

__device__ __constant__ int c_LD[4] = {4, 2, 1, 1};
__device__ __constant__ int c_LH[4] = {48, 24, 12, 6};
__device__ __constant__ int c_LW[4] = {48, 24, 12, 6};

// ---------------- scratch (allocation-free) ----------------
__device__ float g_x  [M_*E_];     // full-precision residual stream
__device__ float g_xr [M_*E_];     // tf32-rounded copy of x (GEMM A)
__device__ float g_pos[M_*E_];
__device__ float g_q  [M_*E_];     // tf32-rounded q = x + pos (GEMM A)
__device__ float g_val[M_*E_];
__device__ float g_sam[M_*E_];     // tf32-rounded sampler output (GEMM A)
__device__ float g_tmp[M_*E_];
__device__ float g_oa [M_*512];    // packed: [0,384) offsets, [384,512) attn logits
__device__ float g_hid[M_*DF_];    // tf32-rounded (GEMM A)

// pre-rounded packed weights
__device__ float g_Wval[NLAYERS_*E_*E_];
__device__ float g_Wqa [NLAYERS_*E_*512];
__device__ float g_Wout[NLAYERS_*E_*E_];
__device__ float g_Wff1[NLAYERS_*E_*DF_];
__device__ float g_Wff2[NLAYERS_*DF_*E_];
__device__ float g_bqa [NLAYERS_*512];

// ---------------- tf32 helpers ----------------
__device__ __forceinline__ unsigned tf32_bits(float x)
{
    unsigned r;
    asm("cvt.rna.tf32.f32 %0, %1;\n" : "=r"(r) : "f"(x));
    return r;
}
__device__ __forceinline__ float tf32_round(float x)
{
    return __uint_as_float(tf32_bits(x));
}

__device__ __forceinline__ void mma_tf32(float c[4], const unsigned a[4], const unsigned b[2])
{
    asm volatile("mma.sync.aligned.m16n8k8.row.col.f32.tf32.tf32.f32 "
        "{%0,%1,%2,%3}, {%4,%5,%6,%7}, {%8,%9}, {%0,%1,%2,%3};\n"
        : "+f"(c[0]), "+f"(c[1]), "+f"(c[2]), "+f"(c[3])
        : "r"(a[0]), "r"(a[1]), "r"(a[2]), "r"(a[3]), "r"(b[0]), "r"(b[1]));
}

__device__ __forceinline__ void cp_async16(float* smem, const float* gmem, bool valid)
{
    unsigned saddr = (unsigned)__cvta_generic_to_shared(smem);
    int sz = valid ? 16 : 0;
    asm volatile("cp.async.cg.shared.global [%0], [%1], 16, %2;\n"
                 :: "r"(saddr), "l"(gmem), "r"(sz));
}
__device__ __forceinline__ void cp_commit() { asm volatile("cp.async.commit_group;\n"); }
template<int N> __device__ __forceinline__ void cp_wait() { asm volatile("cp.async.wait_group %0;\n" :: "n"(N)); }

#define LDSM_X4(r0,r1,r2,r3,addr) \
    asm volatile("ldmatrix.sync.aligned.m8n8.x4.shared.b16 {%0,%1,%2,%3}, [%4];\n" \
        : "=r"(r0), "=r"(r1), "=r"(r2), "=r"(r3) : "r"(addr))

// ---------------- weight pack / round kernels ----------------
__global__ void roundcopy_kernel(float* __restrict__ dst, const float* __restrict__ src, int n)
{
    int i = blockIdx.x * blockDim.x + threadIdx.x;
    if (i < n) dst[i] = tf32_round(src[i]);
}

__global__ void pack_qa_kernel(const float* __restrict__ Woff, const float* __restrict__ Wattn,
                               const float* __restrict__ boff, const float* __restrict__ battn)
{
    int idx = blockIdx.x * blockDim.x + threadIdx.x;
    int tot = NLAYERS_ * E_ * 512;
    if (idx < tot) {
        int l = idx / (E_ * 512);
        int rem = idx - l * E_ * 512;
        int k = rem >> 9;
        int c = rem & 511;
        float v = (c < 384) ? Woff[(size_t)l*E_*384 + k*384 + c]
                            : Wattn[(size_t)l*E_*128 + k*128 + (c - 384)];
        g_Wqa[idx] = tf32_round(v);
    }
    if (idx < NLAYERS_ * 512) {
        int l = idx >> 9;
        int c = idx & 511;
        g_bqa[idx] = (c < 384) ? boff[l*384 + c] : battn[l*128 + (c - 384)];
    }
}

// ---------------- coalesced transposing init (per level) ----------------
__global__ void init_t_kernel(const float* __restrict__ f, const float* __restrict__ p,
                              const float* __restrict__ le_row, int n, int s0)
{
    __shared__ float tf[32][33];
    __shared__ float tp[32][33];
    int i0 = blockIdx.x * 32;
    int e0 = blockIdx.y * 32;
    int b  = blockIdx.z;
    int tx = threadIdx.x, ty = threadIdx.y;

    int ig = i0 + tx;
    int eg = e0 + ty;
    if (ig < n) {
        size_t src = (size_t)(b*E_ + eg) * n + ig;
        tf[ty][tx] = f[src];
        tp[ty][tx] = p[src];
    }
    __syncthreads();

    int iw = i0 + ty;
    int ew = e0 + tx;
    if (iw < n) {
        size_t dst = (size_t)(b*S_ + s0 + iw) * E_ + ew;
        float xv = tf[tx][ty];
        float pv = tp[tx][ty] + le_row[ew];
        g_x[dst]   = xv;
        g_xr[dst]  = tf32_round(xv);
        g_pos[dst] = pv;
        g_q[dst]   = tf32_round(xv + pv);
    }
}

// ---------------- tf32 tensor-core GEMM, 3-stage cp.async, ldmatrix A ------
// C[M,N] = A @ W[K,N] + bias. mode: 0=none, 1=relu+tf32round (ff1)
#define BM 128
#define BN 128
#define BK 32
#define ASTR 36
#define BSTR 136
#define A_FL (BM*ASTR)        // 4608
#define B_FL (BK*BSTR)        // 4352
#define STG (A_FL + B_FL)     // 8960 floats
#define NSTAGE 3
#define GEMM_SMEM (NSTAGE*STG*4)   // 107520 bytes

__global__ void __launch_bounds__(256, 2)
mma_gemm(const float* __restrict__ A, const float* __restrict__ W,
         const float* __restrict__ bias, float* __restrict__ C,
         int M, int N, int K, int mode)
{
    extern __shared__ float smp[];

    int tid  = threadIdx.x;
    int lane = tid & 31;
    int wid  = tid >> 5;
    int bm = blockIdx.y * BM;
    int bn = blockIdx.x * BN;
    int wm = (wid >> 2) * 64;   // 2 warp-rows of 64
    int wn = (wid & 3) * 32;    // 4 warp-cols of 32
    int q = lane >> 2;          // 0..7
    int r = lane & 3;           // 0..3

    float acc[4][4][4];
    #pragma unroll
    for (int mi = 0; mi < 4; mi++)
        #pragma unroll
        for (int ni = 0; ni < 4; ni++)
            #pragma unroll
            for (int j = 0; j < 4; j++) acc[mi][ni][j] = 0.f;

    // cp.async maps: A 128x32 (1024 chunks, 4/thr); B 32x128 (1024 chunks, 4/thr)
    int arow[4], ac[4]; bool aval[4];
    #pragma unroll
    for (int i = 0; i < 4; i++) {
        int idx = tid + i*256; arow[i] = idx >> 3; ac[i] = idx & 7;
        aval[i] = (bm + arow[i]) < M;
    }
    int brow[4], bc[4];
    #pragma unroll
    for (int i = 0; i < 4; i++) { int idx = tid + i*256; brow[i] = idx >> 5; bc[i] = idx & 31; }

    int nkt = K / BK;

    // ldmatrix per-thread constants
    int mt = lane >> 3;
    int rbase = (mt & 1)*8 + (lane & 7);
    int koff = (mt >> 1)*4;
    unsigned smem_u32 = (unsigned)__cvta_generic_to_shared(smp);

    // prologue: stages 0 and 1
    {
        float* As = smp;
        float* Bs = smp + A_FL;
        #pragma unroll
        for (int i = 0; i < 4; i++)
            cp_async16(As + arow[i]*ASTR + ac[i]*4,
                       A + (size_t)(aval[i] ? (bm + arow[i]) : 0) * K + ac[i]*4, aval[i]);
        #pragma unroll
        for (int i = 0; i < 4; i++)
            cp_async16(Bs + brow[i]*BSTR + bc[i]*4,
                       W + (size_t)brow[i] * N + bn + bc[i]*4, true);
        cp_commit();
        if (nkt > 1) {
            float* As1 = smp + STG;
            float* Bs1 = As1 + A_FL;
            #pragma unroll
            for (int i = 0; i < 4; i++)
                cp_async16(As1 + arow[i]*ASTR + ac[i]*4,
                           A + (size_t)(aval[i] ? (bm + arow[i]) : 0) * K + BK + ac[i]*4, aval[i]);
            #pragma unroll
            for (int i = 0; i < 4; i++)
                cp_async16(Bs1 + brow[i]*BSTR + bc[i]*4,
                           W + (size_t)(BK + brow[i]) * N + bn + bc[i]*4, true);
        }
        cp_commit();
    }

    for (int kt = 0; kt < nkt; kt++) {
        int st = kt % NSTAGE;
        if (kt + 2 < nkt) {
            int s2 = (kt + 2) % NSTAGE;
            float* As = smp + s2*STG;
            float* Bs = As + A_FL;
            int kg = (kt + 2) * BK;
            #pragma unroll
            for (int i = 0; i < 4; i++)
                cp_async16(As + arow[i]*ASTR + ac[i]*4,
                           A + (size_t)(aval[i] ? (bm + arow[i]) : 0) * K + kg + ac[i]*4, aval[i]);
            #pragma unroll
            for (int i = 0; i < 4; i++)
                cp_async16(Bs + brow[i]*BSTR + bc[i]*4,
                           W + (size_t)(kg + brow[i]) * N + bn + bc[i]*4, true);
        }
        cp_commit();
        cp_wait<2>();
        __syncthreads();

        const float* Bs = smp + st*STG + A_FL;
        unsigned abase = smem_u32 + (unsigned)(st*STG)*4u
                       + (unsigned)((wm + rbase)*ASTR + koff)*4u;

        #pragma unroll
        for (int ks = 0; ks < 4; ks++) {
            unsigned af[4][4], bf[4][2];
            #pragma unroll
            for (int mi = 0; mi < 4; mi++) {
                LDSM_X4(af[mi][0], af[mi][1], af[mi][2], af[mi][3],
                        abase + (unsigned)((mi*16*ASTR + ks*8)*4));
            }
            #pragma unroll
            for (int ni = 0; ni < 4; ni++) {
                bf[ni][0] = __float_as_uint(Bs[(ks*8 + r    )*BSTR + wn + ni*8 + q]);
                bf[ni][1] = __float_as_uint(Bs[(ks*8 + r + 4)*BSTR + wn + ni*8 + q]);
            }
            #pragma unroll
            for (int mi = 0; mi < 4; mi++)
                #pragma unroll
                for (int ni = 0; ni < 4; ni++)
                    mma_tf32(acc[mi][ni], af[mi], bf[ni]);
        }
        __syncthreads();
    }

    // epilogue
    #pragma unroll
    for (int mi = 0; mi < 4; mi++) {
        #pragma unroll
        for (int ni = 0; ni < 4; ni++) {
            int row = bm + wm + mi*16 + q;
            int col = bn + wn + ni*8 + r*2;
            float bx = bias[col], by = bias[col+1];
            if (row < M) {
                float v0 = acc[mi][ni][0] + bx;
                float v1 = acc[mi][ni][1] + by;
                if (mode == 1) { v0 = tf32_round(fmaxf(v0, 0.f)); v1 = tf32_round(fmaxf(v1, 0.f)); }
                *(float2*)&C[(size_t)row * N + col] = make_float2(v0, v1);
            }
            if (row + 8 < M) {
                float v2 = acc[mi][ni][2] + bx;
                float v3 = acc[mi][ni][3] + by;
                if (mode == 1) { v2 = tf32_round(fmaxf(v2, 0.f)); v3 = tf32_round(fmaxf(v3, 0.f)); }
                *(float2*)&C[(size_t)(row + 8) * N + col] = make_float2(v2, v3);
            }
        }
    }
}

// ---------------- deformable sampling: warp per (b,s,h), lane = HD element ----
__global__ void sample_kernel()
{
    int gwarp = (blockIdx.x * blockDim.x + threadIdx.x) >> 5;
    int lane  = threadIdx.x & 31;
    if (gwarp >= M_ * NH_) return;
    int h  = gwarp & (NH_-1);
    int bs = gwarp >> 3;
    int b  = bs / S_;
    int s  = bs % S_;

    int lvl_q, iq;
    if (s < 9216)       { lvl_q = 0; iq = s;         }
    else if (s < 10368) { lvl_q = 1; iq = s - 9216;  }
    else if (s < 10512) { lvl_q = 2; iq = s - 10368; }
    else                { lvl_q = 3; iq = s - 10512; }
    int Wq = c_LW[lvl_q], Hq = c_LH[lvl_q], Dq = c_LD[lvl_q];
    int xq = iq % Wq;
    int t  = iq / Wq;
    int yq = t % Hq;
    int zq = t / Hq;
    float rx = (xq + 0.5f) / (float)Wq;
    float ry = (yq + 0.5f) / (float)Hq;
    float rz = (zq + 0.5f) / (float)Dq;

    const float* lg = g_oa + (size_t)bs * 512 + 384 + h * (NL_*NP_);
    float lv[16];
    float mx = -1e30f;
    #pragma unroll
    for (int j = 0; j < 16; j++) { lv[j] = lg[j]; mx = fmaxf(mx, lv[j]); }
    float ssum = 0.f;
    #pragma unroll
    for (int j = 0; j < 16; j++) { lv[j] = expf(lv[j] - mx); ssum += lv[j]; }
    float inv = 1.f / ssum;

    const float* offp = g_oa + (size_t)bs * 512 + h * (NL_*NP_*3);

    const int LDc[4]  = {4, 2, 1, 1};
    const int LHc[4]  = {48, 24, 12, 6};
    const int LWc[4]  = {48, 24, 12, 6};
    const int LS0c[4] = {0, 9216, 10368, 10512};

    float acc = 0.f;
    #pragma unroll
    for (int lvl = 0; lvl < 4; lvl++) {
        const int Dl = LDc[lvl], Hl = LHc[lvl], Wl = LWc[lvl];
        const float* vb = g_val + ((size_t)b * S_ + LS0c[lvl]) * E_ + h * HD_ + lane;
        #pragma unroll
        for (int p = 0; p < NP_; p++) {
            float aw = lv[lvl*4 + p] * inv;
            float ox = offp[lvl*12 + p*3 + 0];
            float oy = offp[lvl*12 + p*3 + 1];
            float oz = offp[lvl*12 + p*3 + 2];
            float cx = rx * (float)Wl + ox - 0.5f;
            float cy = ry * (float)Hl + oy - 0.5f;
            float cz = rz * (float)Dl + oz - 0.5f;
            float xf = floorf(cx), yf = floorf(cy), zf = floorf(cz);
            float fx = cx - xf, fy = cy - yf, fz = cz - zf;
            int x0 = (int)xf, y0 = (int)yf, z0 = (int)zf;
            #pragma unroll
            for (int dz = 0; dz < 2; dz++) {
                int iz = z0 + dz;
                if (iz < 0 || iz >= Dl) continue;
                float wz = dz ? fz : 1.f - fz;
                #pragma unroll
                for (int dy = 0; dy < 2; dy++) {
                    int iy = y0 + dy;
                    if (iy < 0 || iy >= Hl) continue;
                    float wy = dy ? fy : 1.f - fy;
                    #pragma unroll
                    for (int dx = 0; dx < 2; dx++) {
                        int ix = x0 + dx;
                        if (ix < 0 || ix >= Wl) continue;
                        float wx = dx ? fx : 1.f - fx;
                        float wgt = aw * wx * wy * wz;
                        acc += wgt * vb[(size_t)((iz*Hl + iy)*Wl + ix) * E_];
                    }
                }
            }
        }
    }
    g_sam[(size_t)bs * E_ + h * HD_ + lane] = tf32_round(acc);
}

// ---------------- fused residual + LayerNorm (+ rounded copies) -------------
__device__ __forceinline__ float warp_sum(float v)
{
    #pragma unroll
    for (int o = 16; o > 0; o >>= 1) v += __shfl_xor_sync(0xFFFFFFFFu, v, o);
    return v;
}

__global__ void ln_kernel(const float* __restrict__ x, const float* __restrict__ r,
                          const float* __restrict__ g, const float* __restrict__ be,
                          float* __restrict__ out, float* __restrict__ outr,
                          const float* __restrict__ pos, float* __restrict__ qout)
{
    int row = blockIdx.x;
    int e = threadIdx.x;
    size_t base = (size_t)row * E_;
    float v = x[base + e] + r[base + e];
    __shared__ float sh[8];
    float ws = warp_sum(v);
    int w = e >> 5, ln = e & 31;
    if (ln == 0) sh[w] = ws;
    __syncthreads();
    float mean = 0.f;
    #pragma unroll
    for (int i = 0; i < 8; i++) mean += sh[i];
    mean *= (1.f / E_);
    __syncthreads();
    float d = v - mean;
    float ws2 = warp_sum(d * d);
    if (ln == 0) sh[w] = ws2;
    __syncthreads();
    float var = 0.f;
    #pragma unroll
    for (int i = 0; i < 8; i++) var += sh[i];
    var *= (1.f / E_);
    float y = d * rsqrtf(var + 1e-5f) * g[e] + be[e];
    out[base + e] = y;
    if (outr) outr[base + e] = tf32_round(y);
    if (qout) qout[base + e] = tf32_round(y + pos[base + e]);
}

// ---------------- host launcher ----------------
extern "C" void kernel_launch(void* const* d_in, const int* in_sizes, int n_in,
                              void* d_out, int out_size)
{
    (void)in_sizes; (void)n_in; (void)out_size;
    const float* f0 = (const float*)d_in[0];
    const float* p0 = (const float*)d_in[1];
    const float* f1 = (const float*)d_in[2];
    const float* p1 = (const float*)d_in[3];
    const float* f2 = (const float*)d_in[4];
    const float* p2 = (const float*)d_in[5];
    const float* f3 = (const float*)d_in[6];
    const float* p3 = (const float*)d_in[7];
    const float* le = (const float*)d_in[8];
    const float* W_off  = (const float*)d_in[9];
    const float* b_off  = (const float*)d_in[10];
    const float* W_attn = (const float*)d_in[11];
    const float* b_attn = (const float*)d_in[12];
    const float* W_val  = (const float*)d_in[13];
    const float* b_val  = (const float*)d_in[14];
    const float* W_out  = (const float*)d_in[15];
    const float* b_out  = (const float*)d_in[16];
    const float* ln1_g  = (const float*)d_in[17];
    const float* ln1_b  = (const float*)d_in[18];
    const float* W_ff1  = (const float*)d_in[19];
    const float* b_ff1  = (const float*)d_in[20];
    const float* W_ff2  = (const float*)d_in[21];
    const float* b_ff2  = (const float*)d_in[22];
    const float* ln2_g  = (const float*)d_in[23];
    const float* ln2_b  = (const float*)d_in[24];

    float *px, *pxr, *ppos, *pq, *pval, *psam, *ptmp, *phid, *poa;
    float *pWval, *pWqa, *pWout, *pWff1, *pWff2, *pbqa;
    cudaGetSymbolAddress((void**)&px,    g_x);
    cudaGetSymbolAddress((void**)&pxr,   g_xr);
    cudaGetSymbolAddress((void**)&ppos,  g_pos);
    cudaGetSymbolAddress((void**)&pq,    g_q);
    cudaGetSymbolAddress((void**)&pval,  g_val);
    cudaGetSymbolAddress((void**)&psam,  g_sam);
    cudaGetSymbolAddress((void**)&ptmp,  g_tmp);
    cudaGetSymbolAddress((void**)&phid,  g_hid);
    cudaGetSymbolAddress((void**)&poa,   g_oa);
    cudaGetSymbolAddress((void**)&pWval, g_Wval);
    cudaGetSymbolAddress((void**)&pWqa,  g_Wqa);
    cudaGetSymbolAddress((void**)&pWout, g_Wout);
    cudaGetSymbolAddress((void**)&pWff1, g_Wff1);
    cudaGetSymbolAddress((void**)&pWff2, g_Wff2);
    cudaGetSymbolAddress((void**)&pbqa,  g_bqa);

    cudaFuncSetAttribute(mma_gemm, cudaFuncAttributeMaxDynamicSharedMemorySize, GEMM_SMEM);

    // weight pre-rounding / packing
    {
        int n;
        n = NLAYERS_*E_*E_;   roundcopy_kernel<<<(n+255)/256, 256>>>(pWval, W_val, n);
        n = NLAYERS_*E_*E_;   roundcopy_kernel<<<(n+255)/256, 256>>>(pWout, W_out, n);
        n = NLAYERS_*E_*DF_;  roundcopy_kernel<<<(n+255)/256, 256>>>(pWff1, W_ff1, n);
        n = NLAYERS_*DF_*E_;  roundcopy_kernel<<<(n+255)/256, 256>>>(pWff2, W_ff2, n);
        n = NLAYERS_*E_*512;  pack_qa_kernel<<<(n+255)/256, 256>>>(W_off, W_attn, b_off, b_attn);
    }

    // transposing init, one launch per level
    {
        dim3 blk(32, 32);
        init_t_kernel<<<dim3(288, 8, B_), blk>>>(f0, p0, le + 0*E_, 9216, 0);
        init_t_kernel<<<dim3( 36, 8, B_), blk>>>(f1, p1, le + 1*E_, 1152, 9216);
        init_t_kernel<<<dim3(  5, 8, B_), blk>>>(f2, p2, le + 2*E_,  144, 10368);
        init_t_kernel<<<dim3(  2, 8, B_), blk>>>(f3, p3, le + 3*E_,   36, 10512);
    }

    const int GM = (M_ + BM - 1) / BM;   // 165
    for (int l = 0; l < NLAYERS_; l++) {
        // value proj: A = xr
        mma_gemm<<<dim3(E_/BN, GM), 256, GEMM_SMEM>>>(pxr, pWval + (size_t)l*E_*E_,
                                           b_val + l*E_, pval, M_, E_, E_, 0);
        // offsets + attn logits (packed N=512): A = q
        mma_gemm<<<dim3(512/BN, GM), 256, GEMM_SMEM>>>(pq, pWqa + (size_t)l*E_*512,
                                            pbqa + l*512, poa, M_, 512, E_, 0);

        sample_kernel<<<(M_ * NH_ * 32) / 256, 256>>>();

        mma_gemm<<<dim3(E_/BN, GM), 256, GEMM_SMEM>>>(psam, pWout + (size_t)l*E_*E_,
                                           b_out + l*E_, ptmp, M_, E_, E_, 0);
        ln_kernel<<<M_, E_>>>(px, ptmp, ln1_g + l*E_, ln1_b + l*E_, px, pxr,
                              (const float*)0, (float*)0);

        mma_gemm<<<dim3(DF_/BN, GM), 256, GEMM_SMEM>>>(pxr, pWff1 + (size_t)l*E_*DF_,
                                            b_ff1 + l*DF_, phid, M_, DF_, E_, 1);
        mma_gemm<<<dim3(E_/BN, GM), 256, GEMM_SMEM>>>(phid, pWff2 + (size_t)l*DF_*E_,
                                           b_ff2 + l*E_, ptmp, M_, E_, DF_, 0);

        if (l == NLAYERS_ - 1) {
            ln_kernel<<<M_, E_>>>(px, ptmp, ln2_g + l*E_, ln2_b + l*E_,
                                  (float*)d_out, (float*)0, (const float*)0, (float*)0);
        } else {
            ln_kernel<<<M_, E_>>>(px, ptmp, ln2_g + l*E_, ln2_b + l*E_,
                                  px, pxr, ppos, pq);
        }
    }
}

// round 5
// speedup vs baseline: 2.1438x; 1.0551x over previous
#include <cuda_runtime.h>
#include <math.h>
#include <stdint.h>

// ---------------- problem constants ----------------
#define B_ 2
#define E_ 256
#define NH_ 8
#define NL_ 4
#define NP_ 4
#define DF_ 1024
#define NLAYERS_ 6
#define HD_ 32
#define S_ 10548
#define M_ (B_*S_)          // 21096 query rows

__device__ __constant__ int c_LD[4] = {4, 2, 1, 1};
__device__ __constant__ int c_LH[4] = {48, 24, 12, 6};
__device__ __constant__ int c_LW[4] = {48, 24, 12, 6};

// ---------------- scratch (allocation-free) ----------------
__device__ float g_x  [M_*E_];
__device__ float g_xr [M_*E_];
__device__ float g_pos[M_*E_];
__device__ float g_q  [M_*E_];
__device__ float g_val[M_*E_];
__device__ float g_sam[M_*E_];
__device__ float g_tmp[M_*E_];
__device__ float g_oa [M_*512];    // packed: [0,384) offsets, [384,512) attn logits
__device__ float g_hid[M_*DF_];

// pre-rounded packed weights
__device__ float g_Wval[NLAYERS_*E_*E_];
__device__ float g_Wqa [NLAYERS_*E_*512];
__device__ float g_Wout[NLAYERS_*E_*E_];
__device__ float g_Wff1[NLAYERS_*E_*DF_];
__device__ float g_Wff2[NLAYERS_*DF_*E_];
__device__ float g_bqa [NLAYERS_*512];

// ---------------- tf32 helpers ----------------
__device__ __forceinline__ unsigned tf32_bits(float x)
{
    unsigned r;
    asm("cvt.rna.tf32.f32 %0, %1;\n" : "=r"(r) : "f"(x));
    return r;
}
__device__ __forceinline__ float tf32_round(float x)
{
    return __uint_as_float(tf32_bits(x));
}

__device__ __forceinline__ void mma_tf32(float c[4], const unsigned a[4], const unsigned b[2])
{
    asm volatile("mma.sync.aligned.m16n8k8.row.col.f32.tf32.tf32.f32 "
        "{%0,%1,%2,%3}, {%4,%5,%6,%7}, {%8,%9}, {%0,%1,%2,%3};\n"
        : "+f"(c[0]), "+f"(c[1]), "+f"(c[2]), "+f"(c[3])
        : "r"(a[0]), "r"(a[1]), "r"(a[2]), "r"(a[3]), "r"(b[0]), "r"(b[1]));
}

__device__ __forceinline__ void cp_async16(float* smem, const float* gmem, bool valid)
{
    unsigned saddr = (unsigned)__cvta_generic_to_shared(smem);
    int sz = valid ? 16 : 0;
    asm volatile("cp.async.cg.shared.global [%0], [%1], 16, %2;\n"
                 :: "r"(saddr), "l"(gmem), "r"(sz));
}
__device__ __forceinline__ void cp_commit() { asm volatile("cp.async.commit_group;\n"); }
template<int N> __device__ __forceinline__ void cp_wait() { asm volatile("cp.async.wait_group %0;\n" :: "n"(N)); }

#define LDSM_X4(r0,r1,r2,r3,addr) \
    asm volatile("ldmatrix.sync.aligned.m8n8.x4.shared.b16 {%0,%1,%2,%3}, [%4];\n" \
        : "=r"(r0), "=r"(r1), "=r"(r2), "=r"(r3) : "r"(addr))

// ---------------- weight pack / round kernels ----------------
__global__ void roundcopy_kernel(float* __restrict__ dst, const float* __restrict__ src, int n)
{
    int i = blockIdx.x * blockDim.x + threadIdx.x;
    if (i < n) dst[i] = tf32_round(src[i]);
}

__global__ void pack_qa_kernel(const float* __restrict__ Woff, const float* __restrict__ Wattn,
                               const float* __restrict__ boff, const float* __restrict__ battn)
{
    int idx = blockIdx.x * blockDim.x + threadIdx.x;
    int tot = NLAYERS_ * E_ * 512;
    if (idx < tot) {
        int l = idx / (E_ * 512);
        int rem = idx - l * E_ * 512;
        int k = rem >> 9;
        int c = rem & 511;
        float v = (c < 384) ? Woff[(size_t)l*E_*384 + k*384 + c]
                            : Wattn[(size_t)l*E_*128 + k*128 + (c - 384)];
        g_Wqa[idx] = tf32_round(v);
    }
    if (idx < NLAYERS_ * 512) {
        int l = idx >> 9;
        int c = idx & 511;
        g_bqa[idx] = (c < 384) ? boff[l*384 + c] : battn[l*128 + (c - 384)];
    }
}

// ---------------- coalesced transposing init (per level) ----------------
__global__ void init_t_kernel(const float* __restrict__ f, const float* __restrict__ p,
                              const float* __restrict__ le_row, int n, int s0)
{
    __shared__ float tf[32][33];
    __shared__ float tp[32][33];
    int i0 = blockIdx.x * 32;
    int e0 = blockIdx.y * 32;
    int b  = blockIdx.z;
    int tx = threadIdx.x, ty = threadIdx.y;

    int ig = i0 + tx;
    int eg = e0 + ty;
    if (ig < n) {
        size_t src = (size_t)(b*E_ + eg) * n + ig;
        tf[ty][tx] = f[src];
        tp[ty][tx] = p[src];
    }
    __syncthreads();

    int iw = i0 + ty;
    int ew = e0 + tx;
    if (iw < n) {
        size_t dst = (size_t)(b*S_ + s0 + iw) * E_ + ew;
        float xv = tf[tx][ty];
        float pv = tp[tx][ty] + le_row[ew];
        g_x[dst]   = xv;
        g_xr[dst]  = tf32_round(xv);
        g_pos[dst] = pv;
        g_q[dst]   = tf32_round(xv + pv);
    }
}

// ---------------- tf32 tensor-core GEMM, 3-stage cp.async, ldmatrix A ------
// templated block tile; 256 threads, warps 2 rows x 4 cols.
template<int BMt, int BNt>
__global__ void __launch_bounds__(256, (BMt==64 ? 4 : 2))
mma_gemm(const float* __restrict__ A, const float* __restrict__ W,
         const float* __restrict__ bias, float* __restrict__ C,
         int M, int N, int K, int mode)
{
    constexpr int MI   = BMt/32;       // m16 tiles per warp
    constexpr int NI   = BNt/32;       // n8 tiles per warp
    constexpr int ACH  = BMt/32;       // A 16B chunks per thread
    constexpr int BCH  = BNt/32;       // B 16B chunks per thread
    constexpr int CPR  = BNt/4;        // B chunks per k-row
    constexpr int ASTR = 36;
    constexpr int BSTR = BNt + 8;
    constexpr int A_FL = BMt*ASTR;
    constexpr int B_FL = 32*BSTR;
    constexpr int STG  = A_FL + B_FL;

    extern __shared__ float smp[];

    int tid  = threadIdx.x;
    int lane = tid & 31;
    int wid  = tid >> 5;
    int bm = blockIdx.y * BMt;
    int bn = blockIdx.x * BNt;
    int wm = (wid >> 2) * (BMt/2);
    int wn = (wid & 3) * (BNt/4);
    int q = lane >> 2;
    int r = lane & 3;

    float acc[MI][NI][4];
    #pragma unroll
    for (int mi = 0; mi < MI; mi++)
        #pragma unroll
        for (int ni = 0; ni < NI; ni++)
            #pragma unroll
            for (int j = 0; j < 4; j++) acc[mi][ni][j] = 0.f;

    int arow[ACH], ac[ACH]; bool aval[ACH];
    #pragma unroll
    for (int i = 0; i < ACH; i++) {
        int idx = tid + i*256; arow[i] = idx >> 3; ac[i] = idx & 7;
        aval[i] = (bm + arow[i]) < M;
    }
    int brow[BCH], bc[BCH];
    #pragma unroll
    for (int i = 0; i < BCH; i++) { int idx = tid + i*256; brow[i] = idx / CPR; bc[i] = idx % CPR; }

    int nkt = K / 32;

    int mt = lane >> 3;
    int rbase = (mt & 1)*8 + (lane & 7);
    int koff = (mt >> 1)*4;
    unsigned smem_u32 = (unsigned)__cvta_generic_to_shared(smp);

    // prologue: stages 0 and 1
    {
        float* As = smp;
        float* Bs = smp + A_FL;
        #pragma unroll
        for (int i = 0; i < ACH; i++)
            cp_async16(As + arow[i]*ASTR + ac[i]*4,
                       A + (size_t)(aval[i] ? (bm + arow[i]) : 0) * K + ac[i]*4, aval[i]);
        #pragma unroll
        for (int i = 0; i < BCH; i++)
            cp_async16(Bs + brow[i]*BSTR + bc[i]*4,
                       W + (size_t)brow[i] * N + bn + bc[i]*4, true);
        cp_commit();
        if (nkt > 1) {
            float* As1 = smp + STG;
            float* Bs1 = As1 + A_FL;
            #pragma unroll
            for (int i = 0; i < ACH; i++)
                cp_async16(As1 + arow[i]*ASTR + ac[i]*4,
                           A + (size_t)(aval[i] ? (bm + arow[i]) : 0) * K + 32 + ac[i]*4, aval[i]);
            #pragma unroll
            for (int i = 0; i < BCH; i++)
                cp_async16(Bs1 + brow[i]*BSTR + bc[i]*4,
                           W + (size_t)(32 + brow[i]) * N + bn + bc[i]*4, true);
        }
        cp_commit();
    }

    for (int kt = 0; kt < nkt; kt++) {
        int st = kt % 3;
        if (kt + 2 < nkt) {
            int s2 = (kt + 2) % 3;
            float* As = smp + s2*STG;
            float* Bs = As + A_FL;
            int kg = (kt + 2) * 32;
            #pragma unroll
            for (int i = 0; i < ACH; i++)
                cp_async16(As + arow[i]*ASTR + ac[i]*4,
                           A + (size_t)(aval[i] ? (bm + arow[i]) : 0) * K + kg + ac[i]*4, aval[i]);
            #pragma unroll
            for (int i = 0; i < BCH; i++)
                cp_async16(Bs + brow[i]*BSTR + bc[i]*4,
                           W + (size_t)(kg + brow[i]) * N + bn + bc[i]*4, true);
        }
        cp_commit();
        cp_wait<2>();
        __syncthreads();

        const float* Bs = smp + st*STG + A_FL;
        unsigned abase = smem_u32 + (unsigned)(st*STG)*4u
                       + (unsigned)((wm + rbase)*ASTR + koff)*4u;

        #pragma unroll
        for (int ks = 0; ks < 4; ks++) {
            unsigned af[MI][4], bf[NI][2];
            #pragma unroll
            for (int mi = 0; mi < MI; mi++) {
                LDSM_X4(af[mi][0], af[mi][1], af[mi][2], af[mi][3],
                        abase + (unsigned)((mi*16*ASTR + ks*8)*4));
            }
            #pragma unroll
            for (int ni = 0; ni < NI; ni++) {
                bf[ni][0] = __float_as_uint(Bs[(ks*8 + r    )*BSTR + wn + ni*8 + q]);
                bf[ni][1] = __float_as_uint(Bs[(ks*8 + r + 4)*BSTR + wn + ni*8 + q]);
            }
            #pragma unroll
            for (int mi = 0; mi < MI; mi++)
                #pragma unroll
                for (int ni = 0; ni < NI; ni++)
                    mma_tf32(acc[mi][ni], af[mi], bf[ni]);
        }
        __syncthreads();
    }

    // epilogue
    #pragma unroll
    for (int mi = 0; mi < MI; mi++) {
        #pragma unroll
        for (int ni = 0; ni < NI; ni++) {
            int row = bm + wm + mi*16 + q;
            int col = bn + wn + ni*8 + r*2;
            float bx = bias[col], by = bias[col+1];
            if (row < M) {
                float v0 = acc[mi][ni][0] + bx;
                float v1 = acc[mi][ni][1] + by;
                if (mode == 1) { v0 = tf32_round(fmaxf(v0, 0.f)); v1 = tf32_round(fmaxf(v1, 0.f)); }
                *(float2*)&C[(size_t)row * N + col] = make_float2(v0, v1);
            }
            if (row + 8 < M) {
                float v2 = acc[mi][ni][2] + bx;
                float v3 = acc[mi][ni][3] + by;
                if (mode == 1) { v2 = tf32_round(fmaxf(v2, 0.f)); v3 = tf32_round(fmaxf(v3, 0.f)); }
                *(float2*)&C[(size_t)(row + 8) * N + col] = make_float2(v2, v3);
            }
        }
    }
}

// ---------------- deformable sampling ----------------
// CTA = 8 warps = 8 consecutive queries, SAME head -> L1 line reuse
__global__ void sample_kernel()
{
    int warpIdx = (blockIdx.x * blockDim.x + threadIdx.x) >> 5;
    int lane  = threadIdx.x & 31;
    if (warpIdx >= M_ * NH_) return;
    int h  = warpIdx / M_;
    int bs = warpIdx - h * M_;
    int b  = bs / S_;
    int s  = bs % S_;

    int lvl_q, iq;
    if (s < 9216)       { lvl_q = 0; iq = s;         }
    else if (s < 10368) { lvl_q = 1; iq = s - 9216;  }
    else if (s < 10512) { lvl_q = 2; iq = s - 10368; }
    else                { lvl_q = 3; iq = s - 10512; }
    int Wq = c_LW[lvl_q], Hq = c_LH[lvl_q], Dq = c_LD[lvl_q];
    int xq = iq % Wq;
    int t  = iq / Wq;
    int yq = t % Hq;
    int zq = t / Hq;
    float rx = (xq + 0.5f) / (float)Wq;
    float ry = (yq + 0.5f) / (float)Hq;
    float rz = (zq + 0.5f) / (float)Dq;

    // softmax over 16 logits (float4 loads)
    const float4* lg4 = (const float4*)(g_oa + (size_t)bs * 512 + 384 + h * 16);
    float lv[16];
    {
        float4 v0 = lg4[0], v1 = lg4[1], v2 = lg4[2], v3 = lg4[3];
        lv[0]=v0.x; lv[1]=v0.y; lv[2]=v0.z; lv[3]=v0.w;
        lv[4]=v1.x; lv[5]=v1.y; lv[6]=v1.z; lv[7]=v1.w;
        lv[8]=v2.x; lv[9]=v2.y; lv[10]=v2.z; lv[11]=v2.w;
        lv[12]=v3.x; lv[13]=v3.y; lv[14]=v3.z; lv[15]=v3.w;
    }
    float mx = -1e30f;
    #pragma unroll
    for (int j = 0; j < 16; j++) mx = fmaxf(mx, lv[j]);
    float ssum = 0.f;
    #pragma unroll
    for (int j = 0; j < 16; j++) { lv[j] = expf(lv[j] - mx); ssum += lv[j]; }
    float inv = 1.f / ssum;

    const float* offp = g_oa + (size_t)bs * 512 + h * (NL_*NP_*3);

    const int LDc[4]  = {4, 2, 1, 1};
    const int LHc[4]  = {48, 24, 12, 6};
    const int LWc[4]  = {48, 24, 12, 6};
    const int LS0c[4] = {0, 9216, 10368, 10512};

    float acc = 0.f;
    #pragma unroll
    for (int lvl = 0; lvl < 4; lvl++) {
        const int Dl = LDc[lvl], Hl = LHc[lvl], Wl = LWc[lvl];
        const float* vb = g_val + ((size_t)b * S_ + LS0c[lvl]) * E_ + h * HD_ + lane;
        #pragma unroll
        for (int p = 0; p < NP_; p++) {
            float aw = lv[lvl*4 + p] * inv;
            float ox = offp[lvl*12 + p*3 + 0];
            float oy = offp[lvl*12 + p*3 + 1];
            float oz = offp[lvl*12 + p*3 + 2];
            float cx = rx * (float)Wl + ox - 0.5f;
            float cy = ry * (float)Hl + oy - 0.5f;
            float cz = rz * (float)Dl + oz - 0.5f;
            float xf = floorf(cx), yf = floorf(cy), zf = floorf(cz);
            float fx = cx - xf, fy = cy - yf, fz = cz - zf;
            int x0 = (int)xf, y0 = (int)yf, z0 = (int)zf;
            #pragma unroll
            for (int dz = 0; dz < 2; dz++) {
                int iz = z0 + dz;
                if (iz < 0 || iz >= Dl) continue;
                float wz = dz ? fz : 1.f - fz;
                #pragma unroll
                for (int dy = 0; dy < 2; dy++) {
                    int iy = y0 + dy;
                    if (iy < 0 || iy >= Hl) continue;
                    float wy = dy ? fy : 1.f - fy;
                    #pragma unroll
                    for (int dx = 0; dx < 2; dx++) {
                        int ix = x0 + dx;
                        if (ix < 0 || ix >= Wl) continue;
                        float wx = dx ? fx : 1.f - fx;
                        float wgt = aw * wx * wy * wz;
                        acc += wgt * vb[(size_t)((iz*Hl + iy)*Wl + ix) * E_];
                    }
                }
            }
        }
    }
    g_sam[(size_t)bs * E_ + h * HD_ + lane] = tf32_round(acc);
}

// ---------------- fused residual + LayerNorm (+ rounded copies) -------------
__device__ __forceinline__ float warp_sum(float v)
{
    #pragma unroll
    for (int o = 16; o > 0; o >>= 1) v += __shfl_xor_sync(0xFFFFFFFFu, v, o);
    return v;
}

__global__ void ln_kernel(const float* __restrict__ x, const float* __restrict__ r,
                          const float* __restrict__ g, const float* __restrict__ be,
                          float* __restrict__ out, float* __restrict__ outr,
                          const float* __restrict__ pos, float* __restrict__ qout)
{
    int row = blockIdx.x;
    int e = threadIdx.x;
    size_t base = (size_t)row * E_;
    float v = x[base + e] + r[base + e];
    __shared__ float sh[8];
    float ws = warp_sum(v);
    int w = e >> 5, ln = e & 31;
    if (ln == 0) sh[w] = ws;
    __syncthreads();
    float mean = 0.f;
    #pragma unroll
    for (int i = 0; i < 8; i++) mean += sh[i];
    mean *= (1.f / E_);
    __syncthreads();
    float d = v - mean;
    float ws2 = warp_sum(d * d);
    if (ln == 0) sh[w] = ws2;
    __syncthreads();
    float var = 0.f;
    #pragma unroll
    for (int i = 0; i < 8; i++) var += sh[i];
    var *= (1.f / E_);
    float y = d * rsqrtf(var + 1e-5f) * g[e] + be[e];
    out[base + e] = y;
    if (outr) outr[base + e] = tf32_round(y);
    if (qout) qout[base + e] = tf32_round(y + pos[base + e]);
}

// ---------------- host launcher ----------------
#define SMEM128 (3*(128*36 + 32*136)*4)
#define SMEM64  (3*(64*36 + 32*72)*4)

extern "C" void kernel_launch(void* const* d_in, const int* in_sizes, int n_in,
                              void* d_out, int out_size)
{
    (void)in_sizes; (void)n_in; (void)out_size;
    const float* f0 = (const float*)d_in[0];
    const float* p0 = (const float*)d_in[1];
    const float* f1 = (const float*)d_in[2];
    const float* p1 = (const float*)d_in[3];
    const float* f2 = (const float*)d_in[4];
    const float* p2 = (const float*)d_in[5];
    const float* f3 = (const float*)d_in[6];
    const float* p3 = (const float*)d_in[7];
    const float* le = (const float*)d_in[8];
    const float* W_off  = (const float*)d_in[9];
    const float* b_off  = (const float*)d_in[10];
    const float* W_attn = (const float*)d_in[11];
    const float* b_attn = (const float*)d_in[12];
    const float* W_val  = (const float*)d_in[13];
    const float* b_val  = (const float*)d_in[14];
    const float* W_out  = (const float*)d_in[15];
    const float* b_out  = (const float*)d_in[16];
    const float* ln1_g  = (const float*)d_in[17];
    const float* ln1_b  = (const float*)d_in[18];
    const float* W_ff1  = (const float*)d_in[19];
    const float* b_ff1  = (const float*)d_in[20];
    const float* W_ff2  = (const float*)d_in[21];
    const float* b_ff2  = (const float*)d_in[22];
    const float* ln2_g  = (const float*)d_in[23];
    const float* ln2_b  = (const float*)d_in[24];

    float *px, *pxr, *ppos, *pq, *pval, *psam, *ptmp, *phid, *poa;
    float *pWval, *pWqa, *pWout, *pWff1, *pWff2, *pbqa;
    cudaGetSymbolAddress((void**)&px,    g_x);
    cudaGetSymbolAddress((void**)&pxr,   g_xr);
    cudaGetSymbolAddress((void**)&ppos,  g_pos);
    cudaGetSymbolAddress((void**)&pq,    g_q);
    cudaGetSymbolAddress((void**)&pval,  g_val);
    cudaGetSymbolAddress((void**)&psam,  g_sam);
    cudaGetSymbolAddress((void**)&ptmp,  g_tmp);
    cudaGetSymbolAddress((void**)&phid,  g_hid);
    cudaGetSymbolAddress((void**)&poa,   g_oa);
    cudaGetSymbolAddress((void**)&pWval, g_Wval);
    cudaGetSymbolAddress((void**)&pWqa,  g_Wqa);
    cudaGetSymbolAddress((void**)&pWout, g_Wout);
    cudaGetSymbolAddress((void**)&pWff1, g_Wff1);
    cudaGetSymbolAddress((void**)&pWff2, g_Wff2);
    cudaGetSymbolAddress((void**)&pbqa,  g_bqa);

    cudaFuncSetAttribute(mma_gemm<128,128>, cudaFuncAttributeMaxDynamicSharedMemorySize, SMEM128);
    cudaFuncSetAttribute(mma_gemm<64,64>,   cudaFuncAttributeMaxDynamicSharedMemorySize, SMEM64);

    // weight pre-rounding / packing
    {
        int n;
        n = NLAYERS_*E_*E_;   roundcopy_kernel<<<(n+255)/256, 256>>>(pWval, W_val, n);
        n = NLAYERS_*E_*E_;   roundcopy_kernel<<<(n+255)/256, 256>>>(pWout, W_out, n);
        n = NLAYERS_*E_*DF_;  roundcopy_kernel<<<(n+255)/256, 256>>>(pWff1, W_ff1, n);
        n = NLAYERS_*DF_*E_;  roundcopy_kernel<<<(n+255)/256, 256>>>(pWff2, W_ff2, n);
        n = NLAYERS_*E_*512;  pack_qa_kernel<<<(n+255)/256, 256>>>(W_off, W_attn, b_off, b_attn);
    }

    // transposing init, one launch per level
    {
        dim3 blk(32, 32);
        init_t_kernel<<<dim3(288, 8, B_), blk>>>(f0, p0, le + 0*E_, 9216, 0);
        init_t_kernel<<<dim3( 36, 8, B_), blk>>>(f1, p1, le + 1*E_, 1152, 9216);
        init_t_kernel<<<dim3(  5, 8, B_), blk>>>(f2, p2, le + 2*E_,  144, 10368);
        init_t_kernel<<<dim3(  2, 8, B_), blk>>>(f3, p3, le + 3*E_,   36, 10512);
    }

    const int GM64  = (M_ + 63) / 64;    // 330
    const int GM128 = (M_ + 127) / 128;  // 165
    for (int l = 0; l < NLAYERS_; l++) {
        // value proj: N=256, small tiles to kill wave quantization
        mma_gemm<64,64><<<dim3(E_/64, GM64), 256, SMEM64>>>(pxr, pWval + (size_t)l*E_*E_,
                                           b_val + l*E_, pval, M_, E_, E_, 0);
        // offsets + attn logits (packed N=512)
        mma_gemm<128,128><<<dim3(512/128, GM128), 256, SMEM128>>>(pq, pWqa + (size_t)l*E_*512,
                                            pbqa + l*512, poa, M_, 512, E_, 0);

        sample_kernel<<<(M_ * NH_ * 32) / 256, 256>>>();

        mma_gemm<64,64><<<dim3(E_/64, GM64), 256, SMEM64>>>(psam, pWout + (size_t)l*E_*E_,
                                           b_out + l*E_, ptmp, M_, E_, E_, 0);
        ln_kernel<<<M_, E_>>>(px, ptmp, ln1_g + l*E_, ln1_b + l*E_, px, pxr,
                              (const float*)0, (float*)0);

        mma_gemm<128,128><<<dim3(DF_/128, GM128), 256, SMEM128>>>(pxr, pWff1 + (size_t)l*E_*DF_,
                                            b_ff1 + l*DF_, phid, M_, DF_, E_, 1);
        mma_gemm<64,64><<<dim3(E_/64, GM64), 256, SMEM64>>>(phid, pWff2 + (size_t)l*DF_*E_,
                                           b_ff2 + l*E_, ptmp, M_, E_, DF_, 0);

        if (l == NLAYERS_ - 1) {
            ln_kernel<<<M_, E_>>>(px, ptmp, ln2_g + l*E_, ln2_b + l*E_,
                                  (float*)d_out, (float*)0, (const float*)0, (float*)0);
        } else {
            ln_kernel<<<M_, E_>>>(px, ptmp, ln2_g + l*E_, ln2_b + l*E_,
                                  px, pxr, ppos, pq);
        }
    }
}

// round 6
// speedup vs baseline: 2.8381x; 1.3238x over previous
#include <cuda_runtime.h>
#include <math.h>
#include <stdint.h>

// ---------------- problem constants ----------------
#define B_ 2
#define E_ 256
#define NH_ 8
#define NL_ 4
#define NP_ 4
#define DF_ 1024
#define NLAYERS_ 6
#define HD_ 32
#define S_ 10548
#define M_ (B_*S_)          // 21096 query rows

__device__ __constant__ int c_LD[4] = {4, 2, 1, 1};
__device__ __constant__ int c_LH[4] = {48, 24, 12, 6};
__device__ __constant__ int c_LW[4] = {48, 24, 12, 6};

// ---------------- scratch (allocation-free) ----------------
__device__ float g_x  [M_*E_];
__device__ float g_xr [M_*E_];
__device__ float g_pos[M_*E_];
__device__ float g_q  [M_*E_];
__device__ float g_val[M_*E_];
__device__ float g_sam[M_*E_];
__device__ float g_tmp[M_*E_];
__device__ float g_oa [M_*512];    // packed: [0,384) offsets, [384,512) attn logits
__device__ float g_hid[M_*DF_];

// pre-rounded packed weights
__device__ float g_Wval[NLAYERS_*E_*E_];
__device__ float g_Wqa [NLAYERS_*E_*512];
__device__ float g_Wout[NLAYERS_*E_*E_];
__device__ float g_Wff1[NLAYERS_*E_*DF_];
__device__ float g_Wff2[NLAYERS_*DF_*E_];
__device__ float g_bqa [NLAYERS_*512];

// ---------------- tf32 helpers ----------------
__device__ __forceinline__ unsigned tf32_bits(float x)
{
    unsigned r;
    asm("cvt.rna.tf32.f32 %0, %1;\n" : "=r"(r) : "f"(x));
    return r;
}
__device__ __forceinline__ float tf32_round(float x)
{
    return __uint_as_float(tf32_bits(x));
}

__device__ __forceinline__ void mma_tf32(float c[4], const unsigned a[4], const unsigned b[2])
{
    asm volatile("mma.sync.aligned.m16n8k8.row.col.f32.tf32.tf32.f32 "
        "{%0,%1,%2,%3}, {%4,%5,%6,%7}, {%8,%9}, {%0,%1,%2,%3};\n"
        : "+f"(c[0]), "+f"(c[1]), "+f"(c[2]), "+f"(c[3])
        : "r"(a[0]), "r"(a[1]), "r"(a[2]), "r"(a[3]), "r"(b[0]), "r"(b[1]));
}

__device__ __forceinline__ void cp_async16(float* smem, const float* gmem, bool valid)
{
    unsigned saddr = (unsigned)__cvta_generic_to_shared(smem);
    int sz = valid ? 16 : 0;
    asm volatile("cp.async.cg.shared.global [%0], [%1], 16, %2;\n"
                 :: "r"(saddr), "l"(gmem), "r"(sz));
}
__device__ __forceinline__ void cp_commit() { asm volatile("cp.async.commit_group;\n"); }
template<int N> __device__ __forceinline__ void cp_wait() { asm volatile("cp.async.wait_group %0;\n" :: "n"(N)); }

#define LDSM_X4(r0,r1,r2,r3,addr) \
    asm volatile("ldmatrix.sync.aligned.m8n8.x4.shared.b16 {%0,%1,%2,%3}, [%4];\n" \
        : "=r"(r0), "=r"(r1), "=r"(r2), "=r"(r3) : "r"(addr))

// ---------------- weight pack / round kernels ----------------
__global__ void roundcopy_kernel(float* __restrict__ dst, const float* __restrict__ src, int n)
{
    int i = blockIdx.x * blockDim.x + threadIdx.x;
    if (i < n) dst[i] = tf32_round(src[i]);
}

__global__ void pack_qa_kernel(const float* __restrict__ Woff, const float* __restrict__ Wattn,
                               const float* __restrict__ boff, const float* __restrict__ battn)
{
    int idx = blockIdx.x * blockDim.x + threadIdx.x;
    int tot = NLAYERS_ * E_ * 512;
    if (idx < tot) {
        int l = idx / (E_ * 512);
        int rem = idx - l * E_ * 512;
        int k = rem >> 9;
        int c = rem & 511;
        float v = (c < 384) ? Woff[(size_t)l*E_*384 + k*384 + c]
                            : Wattn[(size_t)l*E_*128 + k*128 + (c - 384)];
        g_Wqa[idx] = tf32_round(v);
    }
    if (idx < NLAYERS_ * 512) {
        int l = idx >> 9;
        int c = idx & 511;
        g_bqa[idx] = (c < 384) ? boff[l*384 + c] : battn[l*128 + (c - 384)];
    }
}

// ---------------- coalesced transposing init (per level) ----------------
__global__ void init_t_kernel(const float* __restrict__ f, const float* __restrict__ p,
                              const float* __restrict__ le_row, int n, int s0)
{
    __shared__ float tf[32][33];
    __shared__ float tp[32][33];
    int i0 = blockIdx.x * 32;
    int e0 = blockIdx.y * 32;
    int b  = blockIdx.z;
    int tx = threadIdx.x, ty = threadIdx.y;

    int ig = i0 + tx;
    int eg = e0 + ty;
    if (ig < n) {
        size_t src = (size_t)(b*E_ + eg) * n + ig;
        tf[ty][tx] = f[src];
        tp[ty][tx] = p[src];
    }
    __syncthreads();

    int iw = i0 + ty;
    int ew = e0 + tx;
    if (iw < n) {
        size_t dst = (size_t)(b*S_ + s0 + iw) * E_ + ew;
        float xv = tf[tx][ty];
        float pv = tp[tx][ty] + le_row[ew];
        g_x[dst]   = xv;
        g_xr[dst]  = tf32_round(xv);
        g_pos[dst] = pv;
        g_q[dst]   = tf32_round(xv + pv);
    }
}

// ---------------- tf32 tensor-core GEMM, 3-stage cp.async, ldmatrix A ------
template<int BMt, int BNt>
__global__ void __launch_bounds__(256, (BMt==64 ? 4 : 2))
mma_gemm(const float* __restrict__ A, const float* __restrict__ W,
         const float* __restrict__ bias, float* __restrict__ C,
         int M, int N, int K, int mode)
{
    constexpr int MI   = BMt/32;
    constexpr int NI   = BNt/32;
    constexpr int ACH  = BMt/32;
    constexpr int BCH  = BNt/32;
    constexpr int CPR  = BNt/4;
    constexpr int ASTR = 36;
    constexpr int BSTR = BNt + 8;
    constexpr int A_FL = BMt*ASTR;
    constexpr int B_FL = 32*BSTR;
    constexpr int STG  = A_FL + B_FL;

    extern __shared__ float smp[];

    int tid  = threadIdx.x;
    int lane = tid & 31;
    int wid  = tid >> 5;
    int bm = blockIdx.y * BMt;
    int bn = blockIdx.x * BNt;
    int wm = (wid >> 2) * (BMt/2);
    int wn = (wid & 3) * (BNt/4);
    int q = lane >> 2;
    int r = lane & 3;

    float acc[MI][NI][4];
    #pragma unroll
    for (int mi = 0; mi < MI; mi++)
        #pragma unroll
        for (int ni = 0; ni < NI; ni++)
            #pragma unroll
            for (int j = 0; j < 4; j++) acc[mi][ni][j] = 0.f;

    int arow[ACH], ac[ACH]; bool aval[ACH];
    #pragma unroll
    for (int i = 0; i < ACH; i++) {
        int idx = tid + i*256; arow[i] = idx >> 3; ac[i] = idx & 7;
        aval[i] = (bm + arow[i]) < M;
    }
    int brow[BCH], bc[BCH];
    #pragma unroll
    for (int i = 0; i < BCH; i++) { int idx = tid + i*256; brow[i] = idx / CPR; bc[i] = idx % CPR; }

    int nkt = K / 32;

    int mt = lane >> 3;
    int rbase = (mt & 1)*8 + (lane & 7);
    int koff = (mt >> 1)*4;
    unsigned smem_u32 = (unsigned)__cvta_generic_to_shared(smp);

    {
        float* As = smp;
        float* Bs = smp + A_FL;
        #pragma unroll
        for (int i = 0; i < ACH; i++)
            cp_async16(As + arow[i]*ASTR + ac[i]*4,
                       A + (size_t)(aval[i] ? (bm + arow[i]) : 0) * K + ac[i]*4, aval[i]);
        #pragma unroll
        for (int i = 0; i < BCH; i++)
            cp_async16(Bs + brow[i]*BSTR + bc[i]*4,
                       W + (size_t)brow[i] * N + bn + bc[i]*4, true);
        cp_commit();
        if (nkt > 1) {
            float* As1 = smp + STG;
            float* Bs1 = As1 + A_FL;
            #pragma unroll
            for (int i = 0; i < ACH; i++)
                cp_async16(As1 + arow[i]*ASTR + ac[i]*4,
                           A + (size_t)(aval[i] ? (bm + arow[i]) : 0) * K + 32 + ac[i]*4, aval[i]);
            #pragma unroll
            for (int i = 0; i < BCH; i++)
                cp_async16(Bs1 + brow[i]*BSTR + bc[i]*4,
                           W + (size_t)(32 + brow[i]) * N + bn + bc[i]*4, true);
        }
        cp_commit();
    }

    for (int kt = 0; kt < nkt; kt++) {
        int st = kt % 3;
        if (kt + 2 < nkt) {
            int s2 = (kt + 2) % 3;
            float* As = smp + s2*STG;
            float* Bs = As + A_FL;
            int kg = (kt + 2) * 32;
            #pragma unroll
            for (int i = 0; i < ACH; i++)
                cp_async16(As + arow[i]*ASTR + ac[i]*4,
                           A + (size_t)(aval[i] ? (bm + arow[i]) : 0) * K + kg + ac[i]*4, aval[i]);
            #pragma unroll
            for (int i = 0; i < BCH; i++)
                cp_async16(Bs + brow[i]*BSTR + bc[i]*4,
                           W + (size_t)(kg + brow[i]) * N + bn + bc[i]*4, true);
        }
        cp_commit();
        cp_wait<2>();
        __syncthreads();

        const float* Bs = smp + st*STG + A_FL;
        unsigned abase = smem_u32 + (unsigned)(st*STG)*4u
                       + (unsigned)((wm + rbase)*ASTR + koff)*4u;

        #pragma unroll
        for (int ks = 0; ks < 4; ks++) {
            unsigned af[MI][4], bf[NI][2];
            #pragma unroll
            for (int mi = 0; mi < MI; mi++) {
                LDSM_X4(af[mi][0], af[mi][1], af[mi][2], af[mi][3],
                        abase + (unsigned)((mi*16*ASTR + ks*8)*4));
            }
            #pragma unroll
            for (int ni = 0; ni < NI; ni++) {
                bf[ni][0] = __float_as_uint(Bs[(ks*8 + r    )*BSTR + wn + ni*8 + q]);
                bf[ni][1] = __float_as_uint(Bs[(ks*8 + r + 4)*BSTR + wn + ni*8 + q]);
            }
            #pragma unroll
            for (int mi = 0; mi < MI; mi++)
                #pragma unroll
                for (int ni = 0; ni < NI; ni++)
                    mma_tf32(acc[mi][ni], af[mi], bf[ni]);
        }
        __syncthreads();
    }

    #pragma unroll
    for (int mi = 0; mi < MI; mi++) {
        #pragma unroll
        for (int ni = 0; ni < NI; ni++) {
            int row = bm + wm + mi*16 + q;
            int col = bn + wn + ni*8 + r*2;
            float bx = bias[col], by = bias[col+1];
            if (row < M) {
                float v0 = acc[mi][ni][0] + bx;
                float v1 = acc[mi][ni][1] + by;
                if (mode == 1) { v0 = tf32_round(fmaxf(v0, 0.f)); v1 = tf32_round(fmaxf(v1, 0.f)); }
                *(float2*)&C[(size_t)row * N + col] = make_float2(v0, v1);
            }
            if (row + 8 < M) {
                float v2 = acc[mi][ni][2] + bx;
                float v3 = acc[mi][ni][3] + by;
                if (mode == 1) { v2 = tf32_round(fmaxf(v2, 0.f)); v3 = tf32_round(fmaxf(v3, 0.f)); }
                *(float2*)&C[(size_t)(row + 8) * N + col] = make_float2(v2, v3);
            }
        }
    }
}

// ---------------- deformable sampling, float4-vectorized ----------------
// warp = (b,s,h). lane = eg (bits 0-2: element slice of 4) + pg (bits 3-4: point group).
// Iteration it = level; point groups process the 4 points of that level in parallel.
__global__ void sample_kernel()
{
    int warpIdx = (blockIdx.x * blockDim.x + threadIdx.x) >> 5;
    int lane  = threadIdx.x & 31;
    if (warpIdx >= M_ * NH_) return;
    int h  = warpIdx / M_;
    int bs = warpIdx - h * M_;
    int b  = bs / S_;
    int s  = bs % S_;
    int eg = lane & 7;
    int pg = lane >> 3;

    int lvl_q, iq;
    if (s < 9216)       { lvl_q = 0; iq = s;         }
    else if (s < 10368) { lvl_q = 1; iq = s - 9216;  }
    else if (s < 10512) { lvl_q = 2; iq = s - 10368; }
    else                { lvl_q = 3; iq = s - 10512; }
    int Wq = c_LW[lvl_q], Hq = c_LH[lvl_q], Dq = c_LD[lvl_q];
    int xq = iq % Wq;
    int t  = iq / Wq;
    int yq = t % Hq;
    int zq = t / Hq;
    float rx = (xq + 0.5f) / (float)Wq;
    float ry = (yq + 0.5f) / (float)Hq;
    float rz = (zq + 0.5f) / (float)Dq;

    // softmax over 16 logits (warp-uniform broadcast loads)
    const float4* lg4 = (const float4*)(g_oa + (size_t)bs * 512 + 384 + h * 16);
    float lv[16];
    {
        float4 v0 = lg4[0], v1 = lg4[1], v2 = lg4[2], v3 = lg4[3];
        lv[0]=v0.x; lv[1]=v0.y; lv[2]=v0.z; lv[3]=v0.w;
        lv[4]=v1.x; lv[5]=v1.y; lv[6]=v1.z; lv[7]=v1.w;
        lv[8]=v2.x; lv[9]=v2.y; lv[10]=v2.z; lv[11]=v2.w;
        lv[12]=v3.x; lv[13]=v3.y; lv[14]=v3.z; lv[15]=v3.w;
    }
    float mx = -1e30f;
    #pragma unroll
    for (int j = 0; j < 16; j++) mx = fmaxf(mx, lv[j]);
    float ssum = 0.f;
    #pragma unroll
    for (int j = 0; j < 16; j++) { lv[j] = __expf(lv[j] - mx); ssum += lv[j]; }
    float inv = 1.f / ssum;

    const float* offp = g_oa + (size_t)bs * 512 + h * (NL_*NP_*3);

    const int LDc[4]  = {4, 2, 1, 1};
    const int LHc[4]  = {48, 24, 12, 6};
    const int LWc[4]  = {48, 24, 12, 6};
    const int LS0c[4] = {0, 9216, 10368, 10512};

    float4 acc = make_float4(0.f, 0.f, 0.f, 0.f);

    #pragma unroll
    for (int lvl = 0; lvl < 4; lvl++) {
        const int Dl = LDc[lvl], Hl = LHc[lvl], Wl = LWc[lvl];
        const float* vb = g_val + ((size_t)b * S_ + LS0c[lvl]) * E_ + h * HD_ + eg * 4;

        // this lane's point = (lvl, pg)
        float aw = lv[lvl*4 + pg] * inv;
        float ox = offp[lvl*12 + pg*3 + 0];
        float oy = offp[lvl*12 + pg*3 + 1];
        float oz = offp[lvl*12 + pg*3 + 2];
        float cx = rx * (float)Wl + ox - 0.5f;
        float cy = ry * (float)Hl + oy - 0.5f;
        float cz = rz * (float)Dl + oz - 0.5f;
        float xf = floorf(cx), yf = floorf(cy), zf = floorf(cz);
        float fx = cx - xf, fy = cy - yf, fz = cz - zf;
        int x0 = (int)xf, y0 = (int)yf, z0 = (int)zf;

        #pragma unroll
        for (int dz = 0; dz < 2; dz++) {
            int iz = z0 + dz;
            float wz = dz ? fz : 1.f - fz;
            bool vz = (iz >= 0) & (iz < Dl);
            int cz_i = min(max(iz, 0), Dl - 1);
            #pragma unroll
            for (int dy = 0; dy < 2; dy++) {
                int iy = y0 + dy;
                float wy = dy ? fy : 1.f - fy;
                bool vy = (iy >= 0) & (iy < Hl);
                int cy_i = min(max(iy, 0), Hl - 1);
                #pragma unroll
                for (int dx = 0; dx < 2; dx++) {
                    int ix = x0 + dx;
                    float wx = dx ? fx : 1.f - fx;
                    bool vx = (ix >= 0) & (ix < Wl);
                    int cx_i = min(max(ix, 0), Wl - 1);
                    float wgt = (vz & vy & vx) ? (aw * wx * wy * wz) : 0.f;
                    int idx = (cz_i*Hl + cy_i)*Wl + cx_i;
                    float4 v = *(const float4*)(vb + (size_t)idx * E_);
                    acc.x += wgt * v.x;
                    acc.y += wgt * v.y;
                    acc.z += wgt * v.z;
                    acc.w += wgt * v.w;
                }
            }
        }
    }

    // reduce across point groups (lane bits 3,4)
    #pragma unroll
    for (int o = 8; o <= 16; o <<= 1) {
        acc.x += __shfl_xor_sync(0xFFFFFFFFu, acc.x, o);
        acc.y += __shfl_xor_sync(0xFFFFFFFFu, acc.y, o);
        acc.z += __shfl_xor_sync(0xFFFFFFFFu, acc.z, o);
        acc.w += __shfl_xor_sync(0xFFFFFFFFu, acc.w, o);
    }

    if (lane < 8) {
        float4 o4;
        o4.x = tf32_round(acc.x);
        o4.y = tf32_round(acc.y);
        o4.z = tf32_round(acc.z);
        o4.w = tf32_round(acc.w);
        *(float4*)(g_sam + (size_t)bs * E_ + h * HD_ + lane * 4) = o4;
    }
}

// ---------------- fused residual + LayerNorm (+ rounded copies) -------------
__device__ __forceinline__ float warp_sum(float v)
{
    #pragma unroll
    for (int o = 16; o > 0; o >>= 1) v += __shfl_xor_sync(0xFFFFFFFFu, v, o);
    return v;
}

__global__ void ln_kernel(const float* __restrict__ x, const float* __restrict__ r,
                          const float* __restrict__ g, const float* __restrict__ be,
                          float* __restrict__ out, float* __restrict__ outr,
                          const float* __restrict__ pos, float* __restrict__ qout)
{
    int row = blockIdx.x;
    int e = threadIdx.x;
    size_t base = (size_t)row * E_;
    float v = x[base + e] + r[base + e];
    __shared__ float sh[8];
    float ws = warp_sum(v);
    int w = e >> 5, ln = e & 31;
    if (ln == 0) sh[w] = ws;
    __syncthreads();
    float mean = 0.f;
    #pragma unroll
    for (int i = 0; i < 8; i++) mean += sh[i];
    mean *= (1.f / E_);
    __syncthreads();
    float d = v - mean;
    float ws2 = warp_sum(d * d);
    if (ln == 0) sh[w] = ws2;
    __syncthreads();
    float var = 0.f;
    #pragma unroll
    for (int i = 0; i < 8; i++) var += sh[i];
    var *= (1.f / E_);
    float y = d * rsqrtf(var + 1e-5f) * g[e] + be[e];
    out[base + e] = y;
    if (outr) outr[base + e] = tf32_round(y);
    if (qout) qout[base + e] = tf32_round(y + pos[base + e]);
}

// ---------------- host launcher ----------------
#define SMEM128 (3*(128*36 + 32*136)*4)
#define SMEM64  (3*(64*36 + 32*72)*4)

extern "C" void kernel_launch(void* const* d_in, const int* in_sizes, int n_in,
                              void* d_out, int out_size)
{
    (void)in_sizes; (void)n_in; (void)out_size;
    const float* f0 = (const float*)d_in[0];
    const float* p0 = (const float*)d_in[1];
    const float* f1 = (const float*)d_in[2];
    const float* p1 = (const float*)d_in[3];
    const float* f2 = (const float*)d_in[4];
    const float* p2 = (const float*)d_in[5];
    const float* f3 = (const float*)d_in[6];
    const float* p3 = (const float*)d_in[7];
    const float* le = (const float*)d_in[8];
    const float* W_off  = (const float*)d_in[9];
    const float* b_off  = (const float*)d_in[10];
    const float* W_attn = (const float*)d_in[11];
    const float* b_attn = (const float*)d_in[12];
    const float* W_val  = (const float*)d_in[13];
    const float* b_val  = (const float*)d_in[14];
    const float* W_out  = (const float*)d_in[15];
    const float* b_out  = (const float*)d_in[16];
    const float* ln1_g  = (const float*)d_in[17];
    const float* ln1_b  = (const float*)d_in[18];
    const float* W_ff1  = (const float*)d_in[19];
    const float* b_ff1  = (const float*)d_in[20];
    const float* W_ff2  = (const float*)d_in[21];
    const float* b_ff2  = (const float*)d_in[22];
    const float* ln2_g  = (const float*)d_in[23];
    const float* ln2_b  = (const float*)d_in[24];

    float *px, *pxr, *ppos, *pq, *pval, *psam, *ptmp, *phid, *poa;
    float *pWval, *pWqa, *pWout, *pWff1, *pWff2, *pbqa;
    cudaGetSymbolAddress((void**)&px,    g_x);
    cudaGetSymbolAddress((void**)&pxr,   g_xr);
    cudaGetSymbolAddress((void**)&ppos,  g_pos);
    cudaGetSymbolAddress((void**)&pq,    g_q);
    cudaGetSymbolAddress((void**)&pval,  g_val);
    cudaGetSymbolAddress((void**)&psam,  g_sam);
    cudaGetSymbolAddress((void**)&ptmp,  g_tmp);
    cudaGetSymbolAddress((void**)&phid,  g_hid);
    cudaGetSymbolAddress((void**)&poa,   g_oa);
    cudaGetSymbolAddress((void**)&pWval, g_Wval);
    cudaGetSymbolAddress((void**)&pWqa,  g_Wqa);
    cudaGetSymbolAddress((void**)&pWout, g_Wout);
    cudaGetSymbolAddress((void**)&pWff1, g_Wff1);
    cudaGetSymbolAddress((void**)&pWff2, g_Wff2);
    cudaGetSymbolAddress((void**)&pbqa,  g_bqa);

    cudaFuncSetAttribute(mma_gemm<128,128>, cudaFuncAttributeMaxDynamicSharedMemorySize, SMEM128);
    cudaFuncSetAttribute(mma_gemm<64,64>,   cudaFuncAttributeMaxDynamicSharedMemorySize, SMEM64);

    // weight pre-rounding / packing
    {
        int n;
        n = NLAYERS_*E_*E_;   roundcopy_kernel<<<(n+255)/256, 256>>>(pWval, W_val, n);
        n = NLAYERS_*E_*E_;   roundcopy_kernel<<<(n+255)/256, 256>>>(pWout, W_out, n);
        n = NLAYERS_*E_*DF_;  roundcopy_kernel<<<(n+255)/256, 256>>>(pWff1, W_ff1, n);
        n = NLAYERS_*DF_*E_;  roundcopy_kernel<<<(n+255)/256, 256>>>(pWff2, W_ff2, n);
        n = NLAYERS_*E_*512;  pack_qa_kernel<<<(n+255)/256, 256>>>(W_off, W_attn, b_off, b_attn);
    }

    // transposing init, one launch per level
    {
        dim3 blk(32, 32);
        init_t_kernel<<<dim3(288, 8, B_), blk>>>(f0, p0, le + 0*E_, 9216, 0);
        init_t_kernel<<<dim3( 36, 8, B_), blk>>>(f1, p1, le + 1*E_, 1152, 9216);
        init_t_kernel<<<dim3(  5, 8, B_), blk>>>(f2, p2, le + 2*E_,  144, 10368);
        init_t_kernel<<<dim3(  2, 8, B_), blk>>>(f3, p3, le + 3*E_,   36, 10512);
    }

    const int GM64  = (M_ + 63) / 64;    // 330
    const int GM128 = (M_ + 127) / 128;  // 165
    for (int l = 0; l < NLAYERS_; l++) {
        mma_gemm<64,64><<<dim3(E_/64, GM64), 256, SMEM64>>>(pxr, pWval + (size_t)l*E_*E_,
                                           b_val + l*E_, pval, M_, E_, E_, 0);
        mma_gemm<128,128><<<dim3(512/128, GM128), 256, SMEM128>>>(pq, pWqa + (size_t)l*E_*512,
                                            pbqa + l*512, poa, M_, 512, E_, 0);

        sample_kernel<<<(M_ * NH_ * 32) / 256, 256>>>();

        mma_gemm<64,64><<<dim3(E_/64, GM64), 256, SMEM64>>>(psam, pWout + (size_t)l*E_*E_,
                                           b_out + l*E_, ptmp, M_, E_, E_, 0);
        ln_kernel<<<M_, E_>>>(px, ptmp, ln1_g + l*E_, ln1_b + l*E_, px, pxr,
                              (const float*)0, (float*)0);

        mma_gemm<128,128><<<dim3(DF_/128, GM128), 256, SMEM128>>>(pxr, pWff1 + (size_t)l*E_*DF_,
                                            b_ff1 + l*DF_, phid, M_, DF_, E_, 1);
        mma_gemm<64,64><<<dim3(E_/64, GM64), 256, SMEM64>>>(phid, pWff2 + (size_t)l*DF_*E_,
                                           b_ff2 + l*E_, ptmp, M_, E_, DF_, 0);

        if (l == NLAYERS_ - 1) {
            ln_kernel<<<M_, E_>>>(px, ptmp, ln2_g + l*E_, ln2_b + l*E_,
                                  (float*)d_out, (float*)0, (const float*)0, (float*)0);
        } else {
            ln_kernel<<<M_, E_>>>(px, ptmp, ln2_g + l*E_, ln2_b + l*E_,
                                  px, pxr, ppos, pq);
        }
    }
}